// round 14
// baseline (speedup 1.0000x reference)
#include <cuda_runtime.h>
#include <cuda_bf16.h>
#include <math.h>
#include <stdint.h>

#define MODEL_DIM 4096
#define NH 32
#define NG 8
#define HD 128
#define KV_DIM 1024
#define QKV_N (MODEL_DIM + 2 * KV_DIM)    // 6144
#define S_LEN 2048

// ---------------- scratch (__device__ globals; no allocs allowed) ----------
__device__ float4 g_xpk[(S_LEN / 16) * (MODEL_DIM / 8) * 32];       // packed x
__device__ float4 g_apk[(S_LEN / 16) * (MODEL_DIM / 8) * 32];       // packed attn out
__device__ float4 g_wqkvpk[(QKV_N / 16) * (MODEL_DIM / 8) * 32];    // packed Wqkv^T
__device__ float4 g_wopk[(MODEL_DIM / 16) * (MODEL_DIM / 8) * 32];  // packed Wo^T
__device__ float2 g_rope[S_LEN * 64];                               // {cos, sin}
// pre-split bf16 operands for attention (packed per head: [h][s][d])
__device__ __nv_bfloat16 g_qhi[NH * S_LEN * HD];
__device__ __nv_bfloat16 g_qlo[NH * S_LEN * HD];
__device__ __nv_bfloat16 g_khi[NG * S_LEN * HD];
__device__ __nv_bfloat16 g_klo[NG * S_LEN * HD];
__device__ __nv_bfloat16 g_vhi[NG * S_LEN * HD];
__device__ __nv_bfloat16 g_vlo[NG * S_LEN * HD];

// ---------------- helpers --------------------------------------------------
__device__ __forceinline__ uint32_t f2tf32(float x) {
    uint32_t t;
    asm("cvt.rna.tf32.f32 %0, %1;" : "=r"(t) : "f"(x));
    return t;
}
__device__ __forceinline__ float tf32r(float x) { return __uint_as_float(f2tf32(x)); }

__device__ __forceinline__ void mma_tf32(float c[4],
                                         uint32_t a0, uint32_t a1, uint32_t a2, uint32_t a3,
                                         uint32_t b0, uint32_t b1) {
    asm volatile(
        "mma.sync.aligned.m16n8k8.row.col.f32.tf32.tf32.f32 "
        "{%0,%1,%2,%3}, {%4,%5,%6,%7}, {%8,%9}, {%0,%1,%2,%3};\n"
        : "+f"(c[0]), "+f"(c[1]), "+f"(c[2]), "+f"(c[3])
        : "r"(a0), "r"(a1), "r"(a2), "r"(a3), "r"(b0), "r"(b1));
}

__device__ __forceinline__ void cp_async16(uint32_t smem_addr, const void* gptr) {
    asm volatile("cp.async.cg.shared.global [%0], [%1], 16;\n"
                 :: "r"(smem_addr), "l"(gptr));
}

__device__ __forceinline__ void split_bf16(float x, __nv_bfloat16& hi, __nv_bfloat16& lo) {
    hi = __float2bfloat16(x);
    lo = __float2bfloat16(x - __bfloat162float(hi));
}

__device__ __forceinline__ uint32_t pack_bf16x2(__nv_bfloat16 a, __nv_bfloat16 b) {
    __nv_bfloat162 t{a, b};
    return *(uint32_t*)&t;
}

// ---------------------------------------------------------------------------
// RoPE trig table (fp64, computed once per call).
// ---------------------------------------------------------------------------
__global__ __launch_bounds__(64) void rope_table_kernel()
{
    int s = blockIdx.x;
    int d = threadIdx.x;
    double inv = pow(50000.0, -2.0 * (double)d / 128.0);
    double ang = (double)s * inv;
    g_rope[s * 64 + d] = float2{(float)cos(ang), (float)sin(ang)};
}

__global__ void join_kernel() {}

// ---------------------------------------------------------------------------
// Coalesced packing via 64x64 smem transpose tiles (bit-identical values).
// ---------------------------------------------------------------------------
__global__ __launch_bounds__(256) void pack_a_t_kernel(
    const float* __restrict__ A, float4* __restrict__ pk, int M, int K)
{
    __shared__ float ts[64][68];
    const int tid = threadIdx.x;
    const int m0 = blockIdx.y * 64;
    const int k0 = blockIdx.x * 64;
    const int Kt = K >> 3;

#pragma unroll
    for (int i = 0; i < 4; i++) {
        int idx = tid + i * 256;
        int r  = idx >> 4;
        int c4 = (idx & 15) * 4;
        *(float4*)&ts[r][c4] = *(const float4*)&A[(size_t)(m0 + r) * K + k0 + c4];
    }
    __syncthreads();

#pragma unroll
    for (int i = 0; i < 4; i++) {
        int idx  = tid + i * 256;
        int lane = idx & 31;
        int ktl  = (idx >> 5) & 7;
        int mtl  = idx >> 8;
        int rl = mtl * 16 + (lane >> 2);
        int cl = ktl * 8 + (lane & 3);
        float4 v;
        v.x = tf32r(ts[rl][cl]);
        v.y = tf32r(ts[rl + 8][cl]);
        v.z = tf32r(ts[rl][cl + 4]);
        v.w = tf32r(ts[rl + 8][cl + 4]);
        size_t mt_g = (size_t)(m0 >> 4) + mtl;
        size_t kt_g = (size_t)(k0 >> 3) + ktl;
        pk[(mt_g * Kt + kt_g) * 32 + lane] = v;
    }
}

__global__ __launch_bounds__(256) void pack_b_t_kernel(
    const float* __restrict__ W, float4* __restrict__ pk, int K, int N)
{
    __shared__ float ts[64][72];
    const int tid = threadIdx.x;
    const int n0 = blockIdx.x * 64;
    const int k0 = blockIdx.y * 64;
    const int Kt = K >> 3;

#pragma unroll
    for (int i = 0; i < 4; i++) {
        int idx = tid + i * 256;
        int r  = idx >> 4;
        int c4 = (idx & 15) * 4;
        *(float4*)&ts[r][c4] = *(const float4*)&W[(size_t)(k0 + r) * N + n0 + c4];
    }
    __syncthreads();

#pragma unroll
    for (int i = 0; i < 4; i++) {
        int idx  = tid + i * 256;
        int lane = idx & 31;
        int ktl  = (idx >> 5) & 7;
        int npl  = idx >> 8;
        int kl = ktl * 8 + (lane & 3);
        int nl = npl * 16 + (lane >> 2);
        float4 v;
        v.x = tf32r(ts[kl][nl]);
        v.y = tf32r(ts[kl + 4][nl]);
        v.z = tf32r(ts[kl][nl + 8]);
        v.w = tf32r(ts[kl + 4][nl + 8]);
        size_t np_g = (size_t)(n0 >> 4) + npl;
        size_t kt_g = (size_t)(k0 >> 3) + ktl;
        pk[(np_g * Kt + kt_g) * 32 + lane] = v;
    }
}

// ---------------------------------------------------------------------------
// Fragment-packed TF32 GEMM: CTA 128x128, 128 threads, 4 warps (2x2) of 64x64,
// 2-stage cp.async, 3 CTAs/SM.
// FUSED=0: C = A@B + bias. FUSED=1: QKV epilogue with RoPE + bf16 hi/lo split.
// ---------------------------------------------------------------------------
#define GEMM_SMEM (2 * 2048 * 16)   // 65536 B

template<int FUSED>
__global__ __launch_bounds__(128, 3) void gemm_pk_kernel(
    const float4* __restrict__ Apk, const float4* __restrict__ Bpk,
    const float* __restrict__ bias, float* __restrict__ C,
    int M, int N, int K)
{
    extern __shared__ float4 sm4[];
    const int tid  = threadIdx.x;
    const int warp = tid >> 5;
    const int lane = tid & 31;
    const int wm = warp & 1;
    const int wn = warp >> 1;
    const int bm = blockIdx.y * 128;
    const int bn = blockIdx.x * 128;
    const int Kt = K >> 3;
    const uint32_t sbase = (uint32_t)__cvta_generic_to_shared(sm4);

    float acc[4][8][4];
#pragma unroll
    for (int mt = 0; mt < 4; mt++)
#pragma unroll
        for (int nt = 0; nt < 8; nt++)
#pragma unroll
            for (int e = 0; e < 4; e++) acc[mt][nt][e] = 0.f;

    auto load_stage = [&](int buf, int kt0) {
#pragma unroll
        for (int t = 0; t < 8; t++) {
            int c = tid + t * 128;
            int unit = c >> 7, win = c & 127;
            const float4* g = Apk + ((size_t)((bm >> 4) + unit) * Kt + kt0) * 32 + win;
            cp_async16(sbase + (uint32_t)(buf * 2048 + c) * 16, g);
        }
#pragma unroll
        for (int t = 0; t < 8; t++) {
            int c = tid + t * 128;
            int unit = c >> 7, win = c & 127;
            const float4* g = Bpk + ((size_t)((bn >> 4) + unit) * Kt + kt0) * 32 + win;
            cp_async16(sbase + (uint32_t)(buf * 2048 + 1024 + c) * 16, g);
        }
        asm volatile("cp.async.commit_group;\n");
    };

    load_stage(0, 0);

    const int NSt = K >> 5;
    for (int ks = 0; ks < NSt; ks++) {
        if (ks + 1 < NSt) {
            load_stage((ks + 1) & 1, (ks + 1) * 4);
            asm volatile("cp.async.wait_group 1;\n");
        } else {
            asm volatile("cp.async.wait_group 0;\n");
        }
        __syncthreads();

        const float4* As_ = sm4 + (ks & 1) * 2048;
        const float4* Bs_ = As_ + 1024;

#pragma unroll
        for (int kk = 0; kk < 4; kk++) {
            float4 a[4];
#pragma unroll
            for (int mt = 0; mt < 4; mt++)
                a[mt] = As_[((wm * 4 + mt) * 4 + kk) * 32 + lane];
#pragma unroll
            for (int np = 0; np < 4; np++) {
                float4 b = Bs_[((wn * 4 + np) * 4 + kk) * 32 + lane];
                uint32_t b0 = __float_as_uint(b.x);
                uint32_t b1 = __float_as_uint(b.y);
                uint32_t b2 = __float_as_uint(b.z);
                uint32_t b3 = __float_as_uint(b.w);
#pragma unroll
                for (int mt = 0; mt < 4; mt++) {
                    mma_tf32(acc[mt][2 * np],
                             __float_as_uint(a[mt].x), __float_as_uint(a[mt].y),
                             __float_as_uint(a[mt].z), __float_as_uint(a[mt].w),
                             b0, b1);
                    mma_tf32(acc[mt][2 * np + 1],
                             __float_as_uint(a[mt].x), __float_as_uint(a[mt].y),
                             __float_as_uint(a[mt].z), __float_as_uint(a[mt].w),
                             b2, b3);
                }
            }
        }
        __syncthreads();
    }

    if (FUSED == 0) {
#pragma unroll
        for (int mt = 0; mt < 4; mt++) {
            int r0 = bm + wm * 64 + mt * 16 + (lane >> 2);
#pragma unroll
            for (int np = 0; np < 4; np++) {
#pragma unroll
                for (int q = 0; q < 2; q++) {
                    int nt = 2 * np + q;
                    int c = bn + wn * 64 + np * 16 + q * 8 + (lane & 3) * 2;
                    float2 bv = *(const float2*)&bias[c];
                    float2 o0, o1;
                    o0.x = acc[mt][nt][0] + bv.x;
                    o0.y = acc[mt][nt][1] + bv.y;
                    o1.x = acc[mt][nt][2] + bv.x;
                    o1.y = acc[mt][nt][3] + bv.y;
                    *(float2*)&C[(size_t)r0 * N + c]       = o0;
                    *(float2*)&C[(size_t)(r0 + 8) * N + c] = o1;
                }
            }
        }
    } else {
        __syncthreads();
        float* So = (float*)sm4;   // [128][128] fp32 = 64KB
#pragma unroll
        for (int mt = 0; mt < 4; mt++) {
            int rl = wm * 64 + mt * 16 + (lane >> 2);
#pragma unroll
            for (int np = 0; np < 4; np++) {
#pragma unroll
                for (int q = 0; q < 2; q++) {
                    int nt = 2 * np + q;
                    int cl = wn * 64 + np * 16 + q * 8 + (lane & 3) * 2;
                    float2 bv = *(const float2*)&bias[bn + cl];
                    So[rl * 128 + cl]           = acc[mt][nt][0] + bv.x;
                    So[rl * 128 + cl + 1]       = acc[mt][nt][1] + bv.y;
                    So[(rl + 8) * 128 + cl]     = acc[mt][nt][2] + bv.x;
                    So[(rl + 8) * 128 + cl + 1] = acc[mt][nt][3] + bv.y;
                }
            }
        }
        __syncthreads();

        __nv_bfloat16 *dhi, *dlo;
        int mode;         // 0=V(plain) 1=K(rope) 2=Q(rope*scale)
        size_t base;
        if (bn < MODEL_DIM)               { dhi = g_qhi; dlo = g_qlo; base = (size_t)(bn >> 7) * S_LEN * HD; mode = 2; }
        else if (bn < MODEL_DIM + KV_DIM) { dhi = g_khi; dlo = g_klo; base = (size_t)((bn - MODEL_DIM) >> 7) * S_LEN * HD; mode = 1; }
        else                              { dhi = g_vhi; dlo = g_vlo; base = (size_t)((bn - MODEL_DIM - KV_DIM) >> 7) * S_LEN * HD; mode = 0; }
        const float scale = 0.08838834764831843f;

#pragma unroll
        for (int it = 0; it < 32; it++) {
            int idx = tid + it * 128;
            int r = idx >> 5;
            int dp = (idx & 31) * 2;
            int s = bm + r;
            float x1a = So[r * 128 + dp];
            float x1b = So[r * 128 + dp + 1];
            float x2a = So[r * 128 + dp + 64];
            float x2b = So[r * 128 + dp + 65];
            float r1a, r2a, r1b, r2b;
            if (mode == 0) {
                r1a = x1a; r2a = x2a; r1b = x1b; r2b = x2b;
            } else {
                float2 cs0 = g_rope[s * 64 + dp];
                float2 cs1 = g_rope[s * 64 + dp + 1];
                r1a = x1a * cs0.x - x2a * cs0.y;
                r2a = x2a * cs0.x + x1a * cs0.y;
                r1b = x1b * cs1.x - x2b * cs1.y;
                r2b = x2b * cs1.x + x1b * cs1.y;
                if (mode == 2) { r1a *= scale; r2a *= scale; r1b *= scale; r2b *= scale; }
            }
            __nv_bfloat16 h0, l0, h1, l1;
            size_t o = base + (size_t)s * HD + dp;
            split_bf16(r1a, h0, l0); split_bf16(r1b, h1, l1);
            *(__nv_bfloat162*)&dhi[o] = __nv_bfloat162{h0, h1};
            *(__nv_bfloat162*)&dlo[o] = __nv_bfloat162{l0, l1};
            split_bf16(r2a, h0, l0); split_bf16(r2b, h1, l1);
            *(__nv_bfloat162*)&dhi[o + 64] = __nv_bfloat162{h0, h1};
            *(__nv_bfloat162*)&dlo[o + 64] = __nv_bfloat162{l0, l1};
        }
    }
}

// ---------------------------------------------------------------------------
// bf16x3 mma.sync flash attention: Q/P in registers, double-buffered KV with
// KV block 0 prefetch overlapping the Q prologue (Q staged in buf1).
// ---------------------------------------------------------------------------
#define AQ_STRIDE 136
#define BUF_E (4 * 64 * AQ_STRIDE)
#define ATTN_SMEM_BYTES (2 * BUF_E * 2)     // 139264 B

#define LDSM4(R0,R1,R2,R3,ADDR) \
    asm volatile("ldmatrix.sync.aligned.m8n8.x4.shared.b16 {%0,%1,%2,%3}, [%4];" \
                 : "=r"(R0),"=r"(R1),"=r"(R2),"=r"(R3) : "r"(ADDR))
#define LDSM4T(R0,R1,R2,R3,ADDR) \
    asm volatile("ldmatrix.sync.aligned.m8n8.x4.trans.shared.b16 {%0,%1,%2,%3}, [%4];" \
                 : "=r"(R0),"=r"(R1),"=r"(R2),"=r"(R3) : "r"(ADDR))

__device__ __forceinline__ void mma_bf16(float c[4],
                                         uint32_t a0, uint32_t a1, uint32_t a2, uint32_t a3,
                                         uint32_t b0, uint32_t b1) {
    asm volatile(
        "mma.sync.aligned.m16n8k16.row.col.f32.bf16.bf16.f32 "
        "{%0,%1,%2,%3}, {%4,%5,%6,%7}, {%8,%9}, {%0,%1,%2,%3};\n"
        : "+f"(c[0]), "+f"(c[1]), "+f"(c[2]), "+f"(c[3])
        : "r"(a0), "r"(a1), "r"(a2), "r"(a3), "r"(b0), "r"(b1));
}

__global__ __launch_bounds__(256) void attn_mma_kernel(float4* __restrict__ apk, int mb_base)
{
    extern __shared__ __nv_bfloat16 sbm[];
    const uint32_t sb = (uint32_t)__cvta_generic_to_shared(sbm);

    const int tid  = threadIdx.x;
    const int warp = tid >> 5;
    const int lane = tid & 31;
    const int mb = mb_base + (gridDim.x - 1) - blockIdx.x;   // heavy tiles first
    const int h  = blockIdx.y;
    const int kvh = h >> 2;
    const int m0 = mb * 128;

    const __nv_bfloat16* kh_base = g_khi + (size_t)kvh * S_LEN * HD;
    const __nv_bfloat16* kl_base = g_klo + (size_t)kvh * S_LEN * HD;
    const __nv_bfloat16* vh_base = g_vhi + (size_t)kvh * S_LEN * HD;
    const __nv_bfloat16* vl_base = g_vlo + (size_t)kvh * S_LEN * HD;

    auto kv_load = [&](int b, int k0) {
        const uint32_t arr = (uint32_t)(64 * AQ_STRIDE * 2);
#pragma unroll
        for (int t = 0; t < 4; t++) {
            int idx = tid + t * 256;
            int r  = idx >> 4;
            int c8 = (idx & 15) * 8;
            size_t go = (size_t)(k0 + r) * HD + c8;
            uint32_t so = sb + (uint32_t)(b * BUF_E * 2 + (r * AQ_STRIDE + c8) * 2);
            cp_async16(so,           kh_base + go);
            cp_async16(so + arr,     kl_base + go);
            cp_async16(so + 2 * arr, vh_base + go);
            cp_async16(so + 3 * arr, vl_base + go);
        }
        asm volatile("cp.async.commit_group;\n");
    };

    // ---- prefetch KV block 0 into buf0, overlapping the Q prologue ----
    kv_load(0, 0);

    // ---- stage Q in buf1 region, load fragments to registers ----
    {
        __nv_bfloat16* Qst_hi = sbm + BUF_E;
        __nv_bfloat16* Qst_lo = sbm + BUF_E + 128 * AQ_STRIDE;
        const __nv_bfloat16* qh = g_qhi + ((size_t)h * S_LEN + m0) * HD;
        const __nv_bfloat16* ql = g_qlo + ((size_t)h * S_LEN + m0) * HD;
#pragma unroll
        for (int t = 0; t < 8; t++) {
            int idx = tid + t * 256;
            int r  = idx >> 4;
            int c8 = (idx & 15) * 8;
            *(uint4*)&Qst_hi[r * AQ_STRIDE + c8] = *(const uint4*)&qh[r * HD + c8];
            *(uint4*)&Qst_lo[r * AQ_STRIDE + c8] = *(const uint4*)&ql[r * HD + c8];
        }
    }
    __syncthreads();

    uint32_t aqh[8][4], aql[8][4];
    const int a_row = warp * 16 + (lane & 15);
    const int a_col8 = (lane >> 4) * 8;
#pragma unroll
    for (int ks = 0; ks < 8; ks++) {
        uint32_t ad = sb + (uint32_t)(BUF_E * 2) +
                      (uint32_t)((a_row * AQ_STRIDE + ks * 16 + a_col8) * 2);
        LDSM4(aqh[ks][0], aqh[ks][1], aqh[ks][2], aqh[ks][3], ad);
        ad += (uint32_t)(128 * AQ_STRIDE * 2);
        LDSM4(aql[ks][0], aql[ks][1], aql[ks][2], aql[ks][3], ad);
    }
    __syncthreads();   // Q frags extracted; buf1 free for kv_load(1)

    float mrow[2] = {-1e30f, -1e30f};
    float lrow[2] = {0.f, 0.f};
    float oacc[16][4];
#pragma unroll
    for (int nt = 0; nt < 16; nt++)
#pragma unroll
        for (int e = 0; e < 4; e++) oacc[nt][e] = 0.f;

    const int row0g = m0 + warp * 16 + (lane >> 2);
    const int row1g = row0g + 8;

    const int nkb = 2 * mb + 2;
    for (int kb = 0; kb < nkb; kb++) {
        const int cur = kb & 1;
        asm volatile("cp.async.wait_group 0;\n");
        __syncthreads();
        if (kb + 1 < nkb) kv_load(1 - cur, (kb + 1) * 64);

        const __nv_bfloat16* KhiC = sbm + cur * BUF_E;
        const __nv_bfloat16* KloC = KhiC + 64 * AQ_STRIDE;
        const __nv_bfloat16* VhiC = KhiC + 2 * 64 * AQ_STRIDE;
        const __nv_bfloat16* VloC = KhiC + 3 * 64 * AQ_STRIDE;
        const int k0 = kb * 64;

        float sacc[8][4];
#pragma unroll
        for (int nt = 0; nt < 8; nt++)
#pragma unroll
            for (int e = 0; e < 4; e++) sacc[nt][e] = 0.f;

#pragma unroll
        for (int ks = 0; ks < 8; ks++) {
#pragma unroll
            for (int ng = 0; ng < 4; ng++) {
                uint32_t bh[4], bl[4];
                uint32_t bd = (uint32_t)__cvta_generic_to_shared(
                    &KhiC[(ng * 16 + (lane & 15)) * AQ_STRIDE + ks * 16 + a_col8]);
                LDSM4(bh[0], bh[1], bh[2], bh[3], bd);
                bd = (uint32_t)__cvta_generic_to_shared(
                    &KloC[(ng * 16 + (lane & 15)) * AQ_STRIDE + ks * 16 + a_col8]);
                LDSM4(bl[0], bl[1], bl[2], bl[3], bd);
                int nt = ng * 2;
                mma_bf16(sacc[nt],   aqh[ks][0],aqh[ks][1],aqh[ks][2],aqh[ks][3], bh[0],bh[2]);
                mma_bf16(sacc[nt],   aqh[ks][0],aqh[ks][1],aqh[ks][2],aqh[ks][3], bl[0],bl[2]);
                mma_bf16(sacc[nt],   aql[ks][0],aql[ks][1],aql[ks][2],aql[ks][3], bh[0],bh[2]);
                mma_bf16(sacc[nt+1], aqh[ks][0],aqh[ks][1],aqh[ks][2],aqh[ks][3], bh[1],bh[3]);
                mma_bf16(sacc[nt+1], aqh[ks][0],aqh[ks][1],aqh[ks][2],aqh[ks][3], bl[1],bl[3]);
                mma_bf16(sacc[nt+1], aql[ks][0],aql[ks][1],aql[ks][2],aql[ks][3], bh[1],bh[3]);
            }
        }

        if (k0 + 63 > m0) {
#pragma unroll
            for (int nt = 0; nt < 8; nt++) {
                int c = k0 + nt * 8 + 2 * (lane & 3);
                if (c     > row0g) sacc[nt][0] = -1e30f;
                if (c + 1 > row0g) sacc[nt][1] = -1e30f;
                if (c     > row1g) sacc[nt][2] = -1e30f;
                if (c + 1 > row1g) sacc[nt][3] = -1e30f;
            }
        }

        float mx0 = -1e30f, mx1 = -1e30f;
#pragma unroll
        for (int nt = 0; nt < 8; nt++) {
            mx0 = fmaxf(mx0, fmaxf(sacc[nt][0], sacc[nt][1]));
            mx1 = fmaxf(mx1, fmaxf(sacc[nt][2], sacc[nt][3]));
        }
        mx0 = fmaxf(mx0, __shfl_xor_sync(0xffffffffu, mx0, 1));
        mx0 = fmaxf(mx0, __shfl_xor_sync(0xffffffffu, mx0, 2));
        mx1 = fmaxf(mx1, __shfl_xor_sync(0xffffffffu, mx1, 1));
        mx1 = fmaxf(mx1, __shfl_xor_sync(0xffffffffu, mx1, 2));

        float mn0 = fmaxf(mrow[0], mx0);
        float mn1 = fmaxf(mrow[1], mx1);
        float al0 = __expf(mrow[0] - mn0);
        float al1 = __expf(mrow[1] - mn1);

        uint32_t pfh[8], pfh2[8], pfl[8], pfl2[8];
        float s0 = 0.f, s1 = 0.f;
#pragma unroll
        for (int nt = 0; nt < 8; nt++) {
            float p00 = __expf(sacc[nt][0] - mn0);
            float p01 = __expf(sacc[nt][1] - mn0);
            float p10 = __expf(sacc[nt][2] - mn1);
            float p11 = __expf(sacc[nt][3] - mn1);
            s0 += p00 + p01;
            s1 += p10 + p11;
            __nv_bfloat16 h0,l0,h1,l1;
            split_bf16(p00,h0,l0); split_bf16(p01,h1,l1);
            pfh[nt] = pack_bf16x2(h0,h1); pfl[nt] = pack_bf16x2(l0,l1);
            split_bf16(p10,h0,l0); split_bf16(p11,h1,l1);
            pfh2[nt] = pack_bf16x2(h0,h1); pfl2[nt] = pack_bf16x2(l0,l1);
        }
        s0 += __shfl_xor_sync(0xffffffffu, s0, 1);
        s0 += __shfl_xor_sync(0xffffffffu, s0, 2);
        s1 += __shfl_xor_sync(0xffffffffu, s1, 1);
        s1 += __shfl_xor_sync(0xffffffffu, s1, 2);

        lrow[0] = lrow[0] * al0 + s0;
        lrow[1] = lrow[1] * al1 + s1;
        mrow[0] = mn0;
        mrow[1] = mn1;
#pragma unroll
        for (int nt = 0; nt < 16; nt++) {
            oacc[nt][0] *= al0; oacc[nt][1] *= al0;
            oacc[nt][2] *= al1; oacc[nt][3] *= al1;
        }

        const int v_row = (lane & 7) + 8 * ((lane >> 3) & 1);
        const int v_col8 = 8 * (lane >> 4);
#pragma unroll
        for (int ks = 0; ks < 4; ks++) {
            int kk = ks * 16;
            uint32_t ah0 = pfh[2*ks],  ah1 = pfh2[2*ks],  ah2 = pfh[2*ks+1],  ah3 = pfh2[2*ks+1];
            uint32_t al0_ = pfl[2*ks], al1_ = pfl2[2*ks], al2_ = pfl[2*ks+1], al3_ = pfl2[2*ks+1];
#pragma unroll
            for (int dg = 0; dg < 8; dg++) {
                int db = dg * 16;
                uint32_t vh[4], vl[4];
                uint32_t vd = (uint32_t)__cvta_generic_to_shared(
                    &VhiC[(kk + v_row) * AQ_STRIDE + db + v_col8]);
                LDSM4T(vh[0], vh[1], vh[2], vh[3], vd);
                vd = (uint32_t)__cvta_generic_to_shared(
                    &VloC[(kk + v_row) * AQ_STRIDE + db + v_col8]);
                LDSM4T(vl[0], vl[1], vl[2], vl[3], vd);
                int nt = dg * 2;
                mma_bf16(oacc[nt],   ah0,ah1,ah2,ah3, vh[0],vh[1]);
                mma_bf16(oacc[nt],   ah0,ah1,ah2,ah3, vl[0],vl[1]);
                mma_bf16(oacc[nt],   al0_,al1_,al2_,al3_, vh[0],vh[1]);
                mma_bf16(oacc[nt+1], ah0,ah1,ah2,ah3, vh[2],vh[3]);
                mma_bf16(oacc[nt+1], ah0,ah1,ah2,ah3, vl[2],vl[3]);
                mma_bf16(oacc[nt+1], al0_,al1_,al2_,al3_, vh[2],vh[3]);
            }
        }
    }

    // ---- epilogue: normalize -> smem staging -> fragment-packed apk ----
    __syncthreads();
    float* So = (float*)sbm;
    {
        float inv0 = 1.f / lrow[0];
        float inv1 = 1.f / lrow[1];
        int r0l = warp * 16 + (lane >> 2);
#pragma unroll
        for (int nt = 0; nt < 16; nt++) {
            int col = nt * 8 + 2 * (lane & 3);
            So[r0l * 132 + col]           = oacc[nt][0] * inv0;
            So[r0l * 132 + col + 1]       = oacc[nt][1] * inv0;
            So[(r0l + 8) * 132 + col]     = oacc[nt][2] * inv1;
            So[(r0l + 8) * 132 + col + 1] = oacc[nt][3] * inv1;
        }
    }
    __syncthreads();

    {
        const int Ktot = MODEL_DIM / 8;
#pragma unroll
        for (int i = 0; i < 16; i++) {
            int idx = tid + i * 256;
            int lane2 = idx & 31;
            int kt_l  = (idx >> 5) & 15;
            int mt_l  = idx >> 9;
            int r = mt_l * 16 + (lane2 >> 2);
            int c = kt_l * 8 + (lane2 & 3);
            float4 v;
            v.x = tf32r(So[r * 132 + c]);
            v.y = tf32r(So[(r + 8) * 132 + c]);
            v.z = tf32r(So[r * 132 + c + 4]);
            v.w = tf32r(So[(r + 8) * 132 + c + 4]);
            size_t mt_g = (size_t)(m0 >> 4) + mt_l;
            size_t kt_g = (size_t)h * 16 + kt_l;
            apk[(mt_g * Ktot + kt_g) * 32 + lane2] = v;
        }
    }
}

// ---------------------------------------------------------------------------
extern "C" void kernel_launch(void* const* d_in, const int* in_sizes, int n_in,
                              void* d_out, int out_size)
{
    const float* x    = (const float*)d_in[0];
    const float* Wqkv = (const float*)d_in[1];
    const float* bqkv = (const float*)d_in[2];
    const float* Wo   = (const float*)d_in[3];
    const float* bo   = (const float*)d_in[4];
    float* out = (float*)d_out;

    float4 *xpk, *apk, *wqpk, *wopk;
    cudaGetSymbolAddress((void**)&xpk, g_xpk);
    cudaGetSymbolAddress((void**)&apk, g_apk);
    cudaGetSymbolAddress((void**)&wqpk, g_wqkvpk);
    cudaGetSymbolAddress((void**)&wopk, g_wopk);

    cudaFuncSetAttribute(gemm_pk_kernel<0>,
                         cudaFuncAttributeMaxDynamicSharedMemorySize, GEMM_SMEM);
    cudaFuncSetAttribute(gemm_pk_kernel<1>,
                         cudaFuncAttributeMaxDynamicSharedMemorySize, GEMM_SMEM);
    cudaFuncSetAttribute(attn_mma_kernel,
                         cudaFuncAttributeMaxDynamicSharedMemorySize, ATTN_SMEM_BYTES);

    static cudaStream_t s_side = nullptr;
    static cudaEvent_t e_fork = nullptr, e_rope = nullptr, e_packs = nullptr,
                       e_wo = nullptr, e_attn1 = nullptr, e_oprojA = nullptr;
    if (!s_side) {
        cudaStreamCreateWithFlags(&s_side, cudaStreamNonBlocking);
        cudaEventCreateWithFlags(&e_fork,   cudaEventDisableTiming);
        cudaEventCreateWithFlags(&e_rope,   cudaEventDisableTiming);
        cudaEventCreateWithFlags(&e_packs,  cudaEventDisableTiming);
        cudaEventCreateWithFlags(&e_wo,     cudaEventDisableTiming);
        cudaEventCreateWithFlags(&e_attn1,  cudaEventDisableTiming);
        cudaEventCreateWithFlags(&e_oprojA, cudaEventDisableTiming);
    }

    const int MB_SPLIT = 10;                 // attention: kernel1 = mb 10..15
    const int ROW_SPLIT = MB_SPLIT * 128;    // 1280
    const int Kt = MODEL_DIM / 8;            // 512

    // ---- fork: side stream runs the tiny rope table first ----
    cudaEventRecord(e_fork, 0);
    cudaStreamWaitEvent(s_side, e_fork, 0);
    rope_table_kernel<<<S_LEN, 64, 0, s_side>>>();
    cudaEventRecord(e_rope, s_side);

    // ---- main stream: critical packs get full DRAM bandwidth ----
    pack_a_t_kernel<<<dim3(MODEL_DIM / 64, S_LEN / 64), 256>>>(x, xpk, S_LEN, MODEL_DIM);
    pack_b_t_kernel<<<dim3(QKV_N / 64, MODEL_DIM / 64), 256>>>(Wqkv, wqpk, MODEL_DIM, QKV_N);
    cudaEventRecord(e_packs, 0);

    // side stream: Wo pack after critical packs -> overlaps compute-bound QKV GEMM
    cudaStreamWaitEvent(s_side, e_packs, 0);
    pack_b_t_kernel<<<dim3(MODEL_DIM / 64, MODEL_DIM / 64), 256, 0, s_side>>>(
        Wo, wopk, MODEL_DIM, MODEL_DIM);
    cudaEventRecord(e_wo, s_side);

    // join rope table (QKV epilogue reads it)
    cudaStreamWaitEvent(0, e_rope, 0);

    // 1) QKV projection with fused RoPE + bf16 split epilogue
    gemm_pk_kernel<1><<<dim3(QKV_N / 128, S_LEN / 128), 128, GEMM_SMEM>>>(
        xpk, wqpk, bqkv, nullptr, S_LEN, QKV_N, MODEL_DIM);

    // 2a) attention heavy half (mb 10..15)
    attn_mma_kernel<<<dim3(S_LEN / 128 - MB_SPLIT, NH), 256, ATTN_SMEM_BYTES>>>(apk, MB_SPLIT);
    cudaEventRecord(e_attn1, 0);

    // side stream: O-proj slice A (rows 1280..2047) overlaps attention light half
    cudaStreamWaitEvent(s_side, e_attn1, 0);
    gemm_pk_kernel<0><<<dim3(MODEL_DIM / 128, (S_LEN - ROW_SPLIT) / 128), 128, GEMM_SMEM, s_side>>>(
        apk + (size_t)(ROW_SPLIT / 16) * Kt * 32, wopk, bo,
        out + (size_t)ROW_SPLIT * MODEL_DIM, S_LEN - ROW_SPLIT, MODEL_DIM, MODEL_DIM);
    cudaEventRecord(e_oprojA, s_side);

    // 2b) attention light half (mb 0..9)
    attn_mma_kernel<<<dim3(MB_SPLIT, NH), 256, ATTN_SMEM_BYTES>>>(apk, 0);

    // 3) O-proj slice B (rows 0..1279) — needs wopk + attention light half
    cudaStreamWaitEvent(0, e_wo, 0);
    gemm_pk_kernel<0><<<dim3(MODEL_DIM / 128, ROW_SPLIT / 128), 128, GEMM_SMEM>>>(
        apk, wopk, bo, out, ROW_SPLIT, MODEL_DIM, MODEL_DIM);

    // join side stream (slice A) before capture ends
    cudaStreamWaitEvent(0, e_oprojA, 0);
    join_kernel<<<1, 1>>>();
}

// round 15
// speedup vs baseline: 1.0831x; 1.0831x over previous
#include <cuda_runtime.h>
#include <cuda_bf16.h>
#include <math.h>
#include <stdint.h>

#define MODEL_DIM 4096
#define NH 32
#define NG 8
#define HD 128
#define KV_DIM 1024
#define QKV_N (MODEL_DIM + 2 * KV_DIM)    // 6144
#define S_LEN 2048

// ---------------- scratch (__device__ globals; no allocs allowed) ----------
__device__ float4 g_xpk[(S_LEN / 16) * (MODEL_DIM / 8) * 32];       // packed x
__device__ float4 g_apk[(S_LEN / 16) * (MODEL_DIM / 8) * 32];       // packed attn out
__device__ float4 g_wqkvpk[(QKV_N / 16) * (MODEL_DIM / 8) * 32];    // packed Wqkv^T
__device__ float4 g_wopk[(MODEL_DIM / 16) * (MODEL_DIM / 8) * 32];  // packed Wo^T
__device__ float2 g_rope[S_LEN * 64];                               // {cos, sin}
// pre-split bf16 operands for attention (packed per head: [h][s][d])
__device__ __nv_bfloat16 g_qhi[NH * S_LEN * HD];
__device__ __nv_bfloat16 g_qlo[NH * S_LEN * HD];
__device__ __nv_bfloat16 g_khi[NG * S_LEN * HD];
__device__ __nv_bfloat16 g_klo[NG * S_LEN * HD];
__device__ __nv_bfloat16 g_vhi[NG * S_LEN * HD];
__device__ __nv_bfloat16 g_vlo[NG * S_LEN * HD];

// ---------------- helpers --------------------------------------------------
__device__ __forceinline__ uint32_t f2tf32(float x) {
    uint32_t t;
    asm("cvt.rna.tf32.f32 %0, %1;" : "=r"(t) : "f"(x));
    return t;
}
__device__ __forceinline__ float tf32r(float x) { return __uint_as_float(f2tf32(x)); }

__device__ __forceinline__ void mma_tf32(float c[4],
                                         uint32_t a0, uint32_t a1, uint32_t a2, uint32_t a3,
                                         uint32_t b0, uint32_t b1) {
    asm volatile(
        "mma.sync.aligned.m16n8k8.row.col.f32.tf32.tf32.f32 "
        "{%0,%1,%2,%3}, {%4,%5,%6,%7}, {%8,%9}, {%0,%1,%2,%3};\n"
        : "+f"(c[0]), "+f"(c[1]), "+f"(c[2]), "+f"(c[3])
        : "r"(a0), "r"(a1), "r"(a2), "r"(a3), "r"(b0), "r"(b1));
}

__device__ __forceinline__ void cp_async16(uint32_t smem_addr, const void* gptr) {
    asm volatile("cp.async.cg.shared.global [%0], [%1], 16;\n"
                 :: "r"(smem_addr), "l"(gptr));
}

__device__ __forceinline__ void split_bf16(float x, __nv_bfloat16& hi, __nv_bfloat16& lo) {
    hi = __float2bfloat16(x);
    lo = __float2bfloat16(x - __bfloat162float(hi));
}

__device__ __forceinline__ uint32_t pack_bf16x2(__nv_bfloat16 a, __nv_bfloat16 b) {
    __nv_bfloat162 t{a, b};
    return *(uint32_t*)&t;
}

// ---------------------------------------------------------------------------
// RoPE trig table (fp64, computed once per call).
// ---------------------------------------------------------------------------
__global__ __launch_bounds__(64) void rope_table_kernel()
{
    int s = blockIdx.x;
    int d = threadIdx.x;
    double inv = pow(50000.0, -2.0 * (double)d / 128.0);
    double ang = (double)s * inv;
    g_rope[s * 64 + d] = float2{(float)cos(ang), (float)sin(ang)};
}

// ---------------------------------------------------------------------------
// Coalesced packing via 64x64 smem transpose tiles (bit-identical values).
// ---------------------------------------------------------------------------
__global__ __launch_bounds__(256) void pack_a_t_kernel(
    const float* __restrict__ A, float4* __restrict__ pk, int M, int K)
{
    __shared__ float ts[64][68];
    const int tid = threadIdx.x;
    const int m0 = blockIdx.y * 64;
    const int k0 = blockIdx.x * 64;
    const int Kt = K >> 3;

#pragma unroll
    for (int i = 0; i < 4; i++) {
        int idx = tid + i * 256;
        int r  = idx >> 4;
        int c4 = (idx & 15) * 4;
        *(float4*)&ts[r][c4] = *(const float4*)&A[(size_t)(m0 + r) * K + k0 + c4];
    }
    __syncthreads();

#pragma unroll
    for (int i = 0; i < 4; i++) {
        int idx  = tid + i * 256;
        int lane = idx & 31;
        int ktl  = (idx >> 5) & 7;
        int mtl  = idx >> 8;
        int rl = mtl * 16 + (lane >> 2);
        int cl = ktl * 8 + (lane & 3);
        float4 v;
        v.x = tf32r(ts[rl][cl]);
        v.y = tf32r(ts[rl + 8][cl]);
        v.z = tf32r(ts[rl][cl + 4]);
        v.w = tf32r(ts[rl + 8][cl + 4]);
        size_t mt_g = (size_t)(m0 >> 4) + mtl;
        size_t kt_g = (size_t)(k0 >> 3) + ktl;
        pk[(mt_g * Kt + kt_g) * 32 + lane] = v;
    }
}

__global__ __launch_bounds__(256) void pack_b_t_kernel(
    const float* __restrict__ W, float4* __restrict__ pk, int K, int N)
{
    __shared__ float ts[64][72];
    const int tid = threadIdx.x;
    const int n0 = blockIdx.x * 64;
    const int k0 = blockIdx.y * 64;
    const int Kt = K >> 3;

#pragma unroll
    for (int i = 0; i < 4; i++) {
        int idx = tid + i * 256;
        int r  = idx >> 4;
        int c4 = (idx & 15) * 4;
        *(float4*)&ts[r][c4] = *(const float4*)&W[(size_t)(k0 + r) * N + n0 + c4];
    }
    __syncthreads();

#pragma unroll
    for (int i = 0; i < 4; i++) {
        int idx  = tid + i * 256;
        int lane = idx & 31;
        int ktl  = (idx >> 5) & 7;
        int npl  = idx >> 8;
        int kl = ktl * 8 + (lane & 3);
        int nl = npl * 16 + (lane >> 2);
        float4 v;
        v.x = tf32r(ts[kl][nl]);
        v.y = tf32r(ts[kl + 4][nl]);
        v.z = tf32r(ts[kl][nl + 8]);
        v.w = tf32r(ts[kl + 4][nl + 8]);
        size_t np_g = (size_t)(n0 >> 4) + npl;
        size_t kt_g = (size_t)(k0 >> 3) + ktl;
        pk[(np_g * Kt + kt_g) * 32 + lane] = v;
    }
}

// ---------------------------------------------------------------------------
// Fragment-packed TF32 GEMM: CTA 128x128, 128 threads, 4 warps (2x2) of 64x64,
// 2-stage cp.async, 3 CTAs/SM.
// FUSED=0: C = A@B + bias. FUSED=1: QKV epilogue with RoPE + bf16 hi/lo split.
// ---------------------------------------------------------------------------
#define GEMM_SMEM (2 * 2048 * 16)   // 65536 B

template<int FUSED>
__global__ __launch_bounds__(128, 3) void gemm_pk_kernel(
    const float4* __restrict__ Apk, const float4* __restrict__ Bpk,
    const float* __restrict__ bias, float* __restrict__ C,
    int M, int N, int K)
{
    extern __shared__ float4 sm4[];
    const int tid  = threadIdx.x;
    const int warp = tid >> 5;
    const int lane = tid & 31;
    const int wm = warp & 1;
    const int wn = warp >> 1;
    const int bm = blockIdx.y * 128;
    const int bn = blockIdx.x * 128;
    const int Kt = K >> 3;
    const uint32_t sbase = (uint32_t)__cvta_generic_to_shared(sm4);

    float acc[4][8][4];
#pragma unroll
    for (int mt = 0; mt < 4; mt++)
#pragma unroll
        for (int nt = 0; nt < 8; nt++)
#pragma unroll
            for (int e = 0; e < 4; e++) acc[mt][nt][e] = 0.f;

    auto load_stage = [&](int buf, int kt0) {
#pragma unroll
        for (int t = 0; t < 8; t++) {
            int c = tid + t * 128;
            int unit = c >> 7, win = c & 127;
            const float4* g = Apk + ((size_t)((bm >> 4) + unit) * Kt + kt0) * 32 + win;
            cp_async16(sbase + (uint32_t)(buf * 2048 + c) * 16, g);
        }
#pragma unroll
        for (int t = 0; t < 8; t++) {
            int c = tid + t * 128;
            int unit = c >> 7, win = c & 127;
            const float4* g = Bpk + ((size_t)((bn >> 4) + unit) * Kt + kt0) * 32 + win;
            cp_async16(sbase + (uint32_t)(buf * 2048 + 1024 + c) * 16, g);
        }
        asm volatile("cp.async.commit_group;\n");
    };

    load_stage(0, 0);

    const int NSt = K >> 5;
    for (int ks = 0; ks < NSt; ks++) {
        if (ks + 1 < NSt) {
            load_stage((ks + 1) & 1, (ks + 1) * 4);
            asm volatile("cp.async.wait_group 1;\n");
        } else {
            asm volatile("cp.async.wait_group 0;\n");
        }
        __syncthreads();

        const float4* As_ = sm4 + (ks & 1) * 2048;
        const float4* Bs_ = As_ + 1024;

#pragma unroll
        for (int kk = 0; kk < 4; kk++) {
            float4 a[4];
#pragma unroll
            for (int mt = 0; mt < 4; mt++)
                a[mt] = As_[((wm * 4 + mt) * 4 + kk) * 32 + lane];
#pragma unroll
            for (int np = 0; np < 4; np++) {
                float4 b = Bs_[((wn * 4 + np) * 4 + kk) * 32 + lane];
                uint32_t b0 = __float_as_uint(b.x);
                uint32_t b1 = __float_as_uint(b.y);
                uint32_t b2 = __float_as_uint(b.z);
                uint32_t b3 = __float_as_uint(b.w);
#pragma unroll
                for (int mt = 0; mt < 4; mt++) {
                    mma_tf32(acc[mt][2 * np],
                             __float_as_uint(a[mt].x), __float_as_uint(a[mt].y),
                             __float_as_uint(a[mt].z), __float_as_uint(a[mt].w),
                             b0, b1);
                    mma_tf32(acc[mt][2 * np + 1],
                             __float_as_uint(a[mt].x), __float_as_uint(a[mt].y),
                             __float_as_uint(a[mt].z), __float_as_uint(a[mt].w),
                             b2, b3);
                }
            }
        }
        __syncthreads();
    }

    if (FUSED == 0) {
#pragma unroll
        for (int mt = 0; mt < 4; mt++) {
            int r0 = bm + wm * 64 + mt * 16 + (lane >> 2);
#pragma unroll
            for (int np = 0; np < 4; np++) {
#pragma unroll
                for (int q = 0; q < 2; q++) {
                    int nt = 2 * np + q;
                    int c = bn + wn * 64 + np * 16 + q * 8 + (lane & 3) * 2;
                    float2 bv = *(const float2*)&bias[c];
                    float2 o0, o1;
                    o0.x = acc[mt][nt][0] + bv.x;
                    o0.y = acc[mt][nt][1] + bv.y;
                    o1.x = acc[mt][nt][2] + bv.x;
                    o1.y = acc[mt][nt][3] + bv.y;
                    *(float2*)&C[(size_t)r0 * N + c]       = o0;
                    *(float2*)&C[(size_t)(r0 + 8) * N + c] = o1;
                }
            }
        }
    } else {
        __syncthreads();
        float* So = (float*)sm4;   // [128][128] fp32 = 64KB
#pragma unroll
        for (int mt = 0; mt < 4; mt++) {
            int rl = wm * 64 + mt * 16 + (lane >> 2);
#pragma unroll
            for (int np = 0; np < 4; np++) {
#pragma unroll
                for (int q = 0; q < 2; q++) {
                    int nt = 2 * np + q;
                    int cl = wn * 64 + np * 16 + q * 8 + (lane & 3) * 2;
                    float2 bv = *(const float2*)&bias[bn + cl];
                    So[rl * 128 + cl]           = acc[mt][nt][0] + bv.x;
                    So[rl * 128 + cl + 1]       = acc[mt][nt][1] + bv.y;
                    So[(rl + 8) * 128 + cl]     = acc[mt][nt][2] + bv.x;
                    So[(rl + 8) * 128 + cl + 1] = acc[mt][nt][3] + bv.y;
                }
            }
        }
        __syncthreads();

        __nv_bfloat16 *dhi, *dlo;
        int mode;         // 0=V(plain) 1=K(rope) 2=Q(rope*scale)
        size_t base;
        if (bn < MODEL_DIM)               { dhi = g_qhi; dlo = g_qlo; base = (size_t)(bn >> 7) * S_LEN * HD; mode = 2; }
        else if (bn < MODEL_DIM + KV_DIM) { dhi = g_khi; dlo = g_klo; base = (size_t)((bn - MODEL_DIM) >> 7) * S_LEN * HD; mode = 1; }
        else                              { dhi = g_vhi; dlo = g_vlo; base = (size_t)((bn - MODEL_DIM - KV_DIM) >> 7) * S_LEN * HD; mode = 0; }
        const float scale = 0.08838834764831843f;

#pragma unroll
        for (int it = 0; it < 32; it++) {
            int idx = tid + it * 128;
            int r = idx >> 5;
            int dp = (idx & 31) * 2;
            int s = bm + r;
            float x1a = So[r * 128 + dp];
            float x1b = So[r * 128 + dp + 1];
            float x2a = So[r * 128 + dp + 64];
            float x2b = So[r * 128 + dp + 65];
            float r1a, r2a, r1b, r2b;
            if (mode == 0) {
                r1a = x1a; r2a = x2a; r1b = x1b; r2b = x2b;
            } else {
                float2 cs0 = g_rope[s * 64 + dp];
                float2 cs1 = g_rope[s * 64 + dp + 1];
                r1a = x1a * cs0.x - x2a * cs0.y;
                r2a = x2a * cs0.x + x1a * cs0.y;
                r1b = x1b * cs1.x - x2b * cs1.y;
                r2b = x2b * cs1.x + x1b * cs1.y;
                if (mode == 2) { r1a *= scale; r2a *= scale; r1b *= scale; r2b *= scale; }
            }
            __nv_bfloat16 h0, l0, h1, l1;
            size_t o = base + (size_t)s * HD + dp;
            split_bf16(r1a, h0, l0); split_bf16(r1b, h1, l1);
            *(__nv_bfloat162*)&dhi[o] = __nv_bfloat162{h0, h1};
            *(__nv_bfloat162*)&dlo[o] = __nv_bfloat162{l0, l1};
            split_bf16(r2a, h0, l0); split_bf16(r2b, h1, l1);
            *(__nv_bfloat162*)&dhi[o + 64] = __nv_bfloat162{h0, h1};
            *(__nv_bfloat162*)&dlo[o + 64] = __nv_bfloat162{l0, l1};
        }
    }
}

// ---------------------------------------------------------------------------
// bf16x3 mma.sync flash attention: Q/P in registers, double-buffered KV,
// KV block 0 prefetched before Q staging (Q staged in buf1).
// Single kernel over all 16 q-tiles, heavy-tiles-first (R13 scheduling).
// ---------------------------------------------------------------------------
#define AQ_STRIDE 136
#define BUF_E (4 * 64 * AQ_STRIDE)
#define ATTN_SMEM_BYTES (2 * BUF_E * 2)     // 139264 B

#define LDSM4(R0,R1,R2,R3,ADDR) \
    asm volatile("ldmatrix.sync.aligned.m8n8.x4.shared.b16 {%0,%1,%2,%3}, [%4];" \
                 : "=r"(R0),"=r"(R1),"=r"(R2),"=r"(R3) : "r"(ADDR))
#define LDSM4T(R0,R1,R2,R3,ADDR) \
    asm volatile("ldmatrix.sync.aligned.m8n8.x4.trans.shared.b16 {%0,%1,%2,%3}, [%4];" \
                 : "=r"(R0),"=r"(R1),"=r"(R2),"=r"(R3) : "r"(ADDR))

__device__ __forceinline__ void mma_bf16(float c[4],
                                         uint32_t a0, uint32_t a1, uint32_t a2, uint32_t a3,
                                         uint32_t b0, uint32_t b1) {
    asm volatile(
        "mma.sync.aligned.m16n8k16.row.col.f32.bf16.bf16.f32 "
        "{%0,%1,%2,%3}, {%4,%5,%6,%7}, {%8,%9}, {%0,%1,%2,%3};\n"
        : "+f"(c[0]), "+f"(c[1]), "+f"(c[2]), "+f"(c[3])
        : "r"(a0), "r"(a1), "r"(a2), "r"(a3), "r"(b0), "r"(b1));
}

__global__ __launch_bounds__(256) void attn_mma_kernel(float4* __restrict__ apk)
{
    extern __shared__ __nv_bfloat16 sbm[];
    const uint32_t sb = (uint32_t)__cvta_generic_to_shared(sbm);

    const int tid  = threadIdx.x;
    const int warp = tid >> 5;
    const int lane = tid & 31;
    const int mb = (gridDim.x - 1) - blockIdx.x;   // heavy tiles first
    const int h  = blockIdx.y;
    const int kvh = h >> 2;
    const int m0 = mb * 128;

    const __nv_bfloat16* kh_base = g_khi + (size_t)kvh * S_LEN * HD;
    const __nv_bfloat16* kl_base = g_klo + (size_t)kvh * S_LEN * HD;
    const __nv_bfloat16* vh_base = g_vhi + (size_t)kvh * S_LEN * HD;
    const __nv_bfloat16* vl_base = g_vlo + (size_t)kvh * S_LEN * HD;

    auto kv_load = [&](int b, int k0) {
        const uint32_t arr = (uint32_t)(64 * AQ_STRIDE * 2);
#pragma unroll
        for (int t = 0; t < 4; t++) {
            int idx = tid + t * 256;
            int r  = idx >> 4;
            int c8 = (idx & 15) * 8;
            size_t go = (size_t)(k0 + r) * HD + c8;
            uint32_t so = sb + (uint32_t)(b * BUF_E * 2 + (r * AQ_STRIDE + c8) * 2);
            cp_async16(so,           kh_base + go);
            cp_async16(so + arr,     kl_base + go);
            cp_async16(so + 2 * arr, vh_base + go);
            cp_async16(so + 3 * arr, vl_base + go);
        }
        asm volatile("cp.async.commit_group;\n");
    };

    // ---- prefetch KV block 0 into buf0, overlapping the Q prologue ----
    kv_load(0, 0);

    // ---- stage Q in buf1 region, load fragments to registers ----
    {
        __nv_bfloat16* Qst_hi = sbm + BUF_E;
        __nv_bfloat16* Qst_lo = sbm + BUF_E + 128 * AQ_STRIDE;
        const __nv_bfloat16* qh = g_qhi + ((size_t)h * S_LEN + m0) * HD;
        const __nv_bfloat16* ql = g_qlo + ((size_t)h * S_LEN + m0) * HD;
#pragma unroll
        for (int t = 0; t < 8; t++) {
            int idx = tid + t * 256;
            int r  = idx >> 4;
            int c8 = (idx & 15) * 8;
            *(uint4*)&Qst_hi[r * AQ_STRIDE + c8] = *(const uint4*)&qh[r * HD + c8];
            *(uint4*)&Qst_lo[r * AQ_STRIDE + c8] = *(const uint4*)&ql[r * HD + c8];
        }
    }
    __syncthreads();

    uint32_t aqh[8][4], aql[8][4];
    const int a_row = warp * 16 + (lane & 15);
    const int a_col8 = (lane >> 4) * 8;
#pragma unroll
    for (int ks = 0; ks < 8; ks++) {
        uint32_t ad = sb + (uint32_t)(BUF_E * 2) +
                      (uint32_t)((a_row * AQ_STRIDE + ks * 16 + a_col8) * 2);
        LDSM4(aqh[ks][0], aqh[ks][1], aqh[ks][2], aqh[ks][3], ad);
        ad += (uint32_t)(128 * AQ_STRIDE * 2);
        LDSM4(aql[ks][0], aql[ks][1], aql[ks][2], aql[ks][3], ad);
    }
    __syncthreads();   // Q frags extracted; buf1 free for kv_load(1)

    float mrow[2] = {-1e30f, -1e30f};
    float lrow[2] = {0.f, 0.f};
    float oacc[16][4];
#pragma unroll
    for (int nt = 0; nt < 16; nt++)
#pragma unroll
        for (int e = 0; e < 4; e++) oacc[nt][e] = 0.f;

    const int row0g = m0 + warp * 16 + (lane >> 2);
    const int row1g = row0g + 8;

    const int nkb = 2 * mb + 2;
    for (int kb = 0; kb < nkb; kb++) {
        const int cur = kb & 1;
        asm volatile("cp.async.wait_group 0;\n");
        __syncthreads();
        if (kb + 1 < nkb) kv_load(1 - cur, (kb + 1) * 64);

        const __nv_bfloat16* KhiC = sbm + cur * BUF_E;
        const __nv_bfloat16* KloC = KhiC + 64 * AQ_STRIDE;
        const __nv_bfloat16* VhiC = KhiC + 2 * 64 * AQ_STRIDE;
        const __nv_bfloat16* VloC = KhiC + 3 * 64 * AQ_STRIDE;
        const int k0 = kb * 64;

        float sacc[8][4];
#pragma unroll
        for (int nt = 0; nt < 8; nt++)
#pragma unroll
            for (int e = 0; e < 4; e++) sacc[nt][e] = 0.f;

#pragma unroll
        for (int ks = 0; ks < 8; ks++) {
#pragma unroll
            for (int ng = 0; ng < 4; ng++) {
                uint32_t bh[4], bl[4];
                uint32_t bd = (uint32_t)__cvta_generic_to_shared(
                    &KhiC[(ng * 16 + (lane & 15)) * AQ_STRIDE + ks * 16 + a_col8]);
                LDSM4(bh[0], bh[1], bh[2], bh[3], bd);
                bd = (uint32_t)__cvta_generic_to_shared(
                    &KloC[(ng * 16 + (lane & 15)) * AQ_STRIDE + ks * 16 + a_col8]);
                LDSM4(bl[0], bl[1], bl[2], bl[3], bd);
                int nt = ng * 2;
                mma_bf16(sacc[nt],   aqh[ks][0],aqh[ks][1],aqh[ks][2],aqh[ks][3], bh[0],bh[2]);
                mma_bf16(sacc[nt],   aqh[ks][0],aqh[ks][1],aqh[ks][2],aqh[ks][3], bl[0],bl[2]);
                mma_bf16(sacc[nt],   aql[ks][0],aql[ks][1],aql[ks][2],aql[ks][3], bh[0],bh[2]);
                mma_bf16(sacc[nt+1], aqh[ks][0],aqh[ks][1],aqh[ks][2],aqh[ks][3], bh[1],bh[3]);
                mma_bf16(sacc[nt+1], aqh[ks][0],aqh[ks][1],aqh[ks][2],aqh[ks][3], bl[1],bl[3]);
                mma_bf16(sacc[nt+1], aql[ks][0],aql[ks][1],aql[ks][2],aql[ks][3], bh[1],bh[3]);
            }
        }

        if (k0 + 63 > m0) {
#pragma unroll
            for (int nt = 0; nt < 8; nt++) {
                int c = k0 + nt * 8 + 2 * (lane & 3);
                if (c     > row0g) sacc[nt][0] = -1e30f;
                if (c + 1 > row0g) sacc[nt][1] = -1e30f;
                if (c     > row1g) sacc[nt][2] = -1e30f;
                if (c + 1 > row1g) sacc[nt][3] = -1e30f;
            }
        }

        float mx0 = -1e30f, mx1 = -1e30f;
#pragma unroll
        for (int nt = 0; nt < 8; nt++) {
            mx0 = fmaxf(mx0, fmaxf(sacc[nt][0], sacc[nt][1]));
            mx1 = fmaxf(mx1, fmaxf(sacc[nt][2], sacc[nt][3]));
        }
        mx0 = fmaxf(mx0, __shfl_xor_sync(0xffffffffu, mx0, 1));
        mx0 = fmaxf(mx0, __shfl_xor_sync(0xffffffffu, mx0, 2));
        mx1 = fmaxf(mx1, __shfl_xor_sync(0xffffffffu, mx1, 1));
        mx1 = fmaxf(mx1, __shfl_xor_sync(0xffffffffu, mx1, 2));

        float mn0 = fmaxf(mrow[0], mx0);
        float mn1 = fmaxf(mrow[1], mx1);
        float al0 = __expf(mrow[0] - mn0);
        float al1 = __expf(mrow[1] - mn1);

        uint32_t pfh[8], pfh2[8], pfl[8], pfl2[8];
        float s0 = 0.f, s1 = 0.f;
#pragma unroll
        for (int nt = 0; nt < 8; nt++) {
            float p00 = __expf(sacc[nt][0] - mn0);
            float p01 = __expf(sacc[nt][1] - mn0);
            float p10 = __expf(sacc[nt][2] - mn1);
            float p11 = __expf(sacc[nt][3] - mn1);
            s0 += p00 + p01;
            s1 += p10 + p11;
            __nv_bfloat16 h0,l0,h1,l1;
            split_bf16(p00,h0,l0); split_bf16(p01,h1,l1);
            pfh[nt] = pack_bf16x2(h0,h1); pfl[nt] = pack_bf16x2(l0,l1);
            split_bf16(p10,h0,l0); split_bf16(p11,h1,l1);
            pfh2[nt] = pack_bf16x2(h0,h1); pfl2[nt] = pack_bf16x2(l0,l1);
        }
        s0 += __shfl_xor_sync(0xffffffffu, s0, 1);
        s0 += __shfl_xor_sync(0xffffffffu, s0, 2);
        s1 += __shfl_xor_sync(0xffffffffu, s1, 1);
        s1 += __shfl_xor_sync(0xffffffffu, s1, 2);

        lrow[0] = lrow[0] * al0 + s0;
        lrow[1] = lrow[1] * al1 + s1;
        mrow[0] = mn0;
        mrow[1] = mn1;
#pragma unroll
        for (int nt = 0; nt < 16; nt++) {
            oacc[nt][0] *= al0; oacc[nt][1] *= al0;
            oacc[nt][2] *= al1; oacc[nt][3] *= al1;
        }

        const int v_row = (lane & 7) + 8 * ((lane >> 3) & 1);
        const int v_col8 = 8 * (lane >> 4);
#pragma unroll
        for (int ks = 0; ks < 4; ks++) {
            int kk = ks * 16;
            uint32_t ah0 = pfh[2*ks],  ah1 = pfh2[2*ks],  ah2 = pfh[2*ks+1],  ah3 = pfh2[2*ks+1];
            uint32_t al0_ = pfl[2*ks], al1_ = pfl2[2*ks], al2_ = pfl[2*ks+1], al3_ = pfl2[2*ks+1];
#pragma unroll
            for (int dg = 0; dg < 8; dg++) {
                int db = dg * 16;
                uint32_t vh[4], vl[4];
                uint32_t vd = (uint32_t)__cvta_generic_to_shared(
                    &VhiC[(kk + v_row) * AQ_STRIDE + db + v_col8]);
                LDSM4T(vh[0], vh[1], vh[2], vh[3], vd);
                vd = (uint32_t)__cvta_generic_to_shared(
                    &VloC[(kk + v_row) * AQ_STRIDE + db + v_col8]);
                LDSM4T(vl[0], vl[1], vl[2], vl[3], vd);
                int nt = dg * 2;
                mma_bf16(oacc[nt],   ah0,ah1,ah2,ah3, vh[0],vh[1]);
                mma_bf16(oacc[nt],   ah0,ah1,ah2,ah3, vl[0],vl[1]);
                mma_bf16(oacc[nt],   al0_,al1_,al2_,al3_, vh[0],vh[1]);
                mma_bf16(oacc[nt+1], ah0,ah1,ah2,ah3, vh[2],vh[3]);
                mma_bf16(oacc[nt+1], ah0,ah1,ah2,ah3, vl[2],vl[3]);
                mma_bf16(oacc[nt+1], al0_,al1_,al2_,al3_, vh[2],vh[3]);
            }
        }
    }

    // ---- epilogue: normalize -> smem staging -> fragment-packed apk ----
    __syncthreads();
    float* So = (float*)sbm;
    {
        float inv0 = 1.f / lrow[0];
        float inv1 = 1.f / lrow[1];
        int r0l = warp * 16 + (lane >> 2);
#pragma unroll
        for (int nt = 0; nt < 16; nt++) {
            int col = nt * 8 + 2 * (lane & 3);
            So[r0l * 132 + col]           = oacc[nt][0] * inv0;
            So[r0l * 132 + col + 1]       = oacc[nt][1] * inv0;
            So[(r0l + 8) * 132 + col]     = oacc[nt][2] * inv1;
            So[(r0l + 8) * 132 + col + 1] = oacc[nt][3] * inv1;
        }
    }
    __syncthreads();

    {
        const int Ktot = MODEL_DIM / 8;
#pragma unroll
        for (int i = 0; i < 16; i++) {
            int idx = tid + i * 256;
            int lane2 = idx & 31;
            int kt_l  = (idx >> 5) & 15;
            int mt_l  = idx >> 9;
            int r = mt_l * 16 + (lane2 >> 2);
            int c = kt_l * 8 + (lane2 & 3);
            float4 v;
            v.x = tf32r(So[r * 132 + c]);
            v.y = tf32r(So[(r + 8) * 132 + c]);
            v.z = tf32r(So[r * 132 + c + 4]);
            v.w = tf32r(So[(r + 8) * 132 + c + 4]);
            size_t mt_g = (size_t)(m0 >> 4) + mt_l;
            size_t kt_g = (size_t)h * 16 + kt_l;
            apk[(mt_g * Ktot + kt_g) * 32 + lane2] = v;
        }
    }
}

// ---------------------------------------------------------------------------
extern "C" void kernel_launch(void* const* d_in, const int* in_sizes, int n_in,
                              void* d_out, int out_size)
{
    const float* x    = (const float*)d_in[0];
    const float* Wqkv = (const float*)d_in[1];
    const float* bqkv = (const float*)d_in[2];
    const float* Wo   = (const float*)d_in[3];
    const float* bo   = (const float*)d_in[4];
    float* out = (float*)d_out;

    float4 *xpk, *apk, *wqpk, *wopk;
    cudaGetSymbolAddress((void**)&xpk, g_xpk);
    cudaGetSymbolAddress((void**)&apk, g_apk);
    cudaGetSymbolAddress((void**)&wqpk, g_wqkvpk);
    cudaGetSymbolAddress((void**)&wopk, g_wopk);

    cudaFuncSetAttribute(gemm_pk_kernel<0>,
                         cudaFuncAttributeMaxDynamicSharedMemorySize, GEMM_SMEM);
    cudaFuncSetAttribute(gemm_pk_kernel<1>,
                         cudaFuncAttributeMaxDynamicSharedMemorySize, GEMM_SMEM);
    cudaFuncSetAttribute(attn_mma_kernel,
                         cudaFuncAttributeMaxDynamicSharedMemorySize, ATTN_SMEM_BYTES);

    static cudaStream_t s_side = nullptr;
    static cudaEvent_t e_fork = nullptr, e_rope = nullptr, e_packs = nullptr, e_wo = nullptr;
    if (!s_side) {
        cudaStreamCreateWithFlags(&s_side, cudaStreamNonBlocking);
        cudaEventCreateWithFlags(&e_fork,  cudaEventDisableTiming);
        cudaEventCreateWithFlags(&e_rope,  cudaEventDisableTiming);
        cudaEventCreateWithFlags(&e_packs, cudaEventDisableTiming);
        cudaEventCreateWithFlags(&e_wo,    cudaEventDisableTiming);
    }

    // ---- fork: side stream runs the tiny rope table first ----
    cudaEventRecord(e_fork, 0);
    cudaStreamWaitEvent(s_side, e_fork, 0);
    rope_table_kernel<<<S_LEN, 64, 0, s_side>>>();
    cudaEventRecord(e_rope, s_side);

    // ---- main stream: critical packs get full DRAM bandwidth ----
    pack_a_t_kernel<<<dim3(MODEL_DIM / 64, S_LEN / 64), 256>>>(x, xpk, S_LEN, MODEL_DIM);
    pack_b_t_kernel<<<dim3(QKV_N / 64, MODEL_DIM / 64), 256>>>(Wqkv, wqpk, MODEL_DIM, QKV_N);
    cudaEventRecord(e_packs, 0);

    // side stream: Wo pack after critical packs -> overlaps compute-bound QKV GEMM
    cudaStreamWaitEvent(s_side, e_packs, 0);
    pack_b_t_kernel<<<dim3(MODEL_DIM / 64, MODEL_DIM / 64), 256, 0, s_side>>>(
        Wo, wopk, MODEL_DIM, MODEL_DIM);
    cudaEventRecord(e_wo, s_side);

    // join rope table (QKV epilogue reads it)
    cudaStreamWaitEvent(0, e_rope, 0);

    // 1) QKV projection with fused RoPE + bf16 split epilogue
    gemm_pk_kernel<1><<<dim3(QKV_N / 128, S_LEN / 128), 128, GEMM_SMEM>>>(
        xpk, wqpk, bqkv, nullptr, S_LEN, QKV_N, MODEL_DIM);

    // 2) attention (bf16x3 mma.sync, register-resident P) -> packed tf32
    attn_mma_kernel<<<dim3(S_LEN / 128, NH), 256, ATTN_SMEM_BYTES>>>(apk);

    // join Wo pack before O-proj
    cudaStreamWaitEvent(0, e_wo, 0);

    // 3) output projection
    gemm_pk_kernel<0><<<dim3(MODEL_DIM / 128, S_LEN / 128), 128, GEMM_SMEM>>>(
        apk, wopk, bo, out, S_LEN, MODEL_DIM, MODEL_DIM);
}

// round 16
// speedup vs baseline: 1.0839x; 1.0007x over previous
#include <cuda_runtime.h>
#include <cuda_bf16.h>
#include <math.h>
#include <stdint.h>

#define MODEL_DIM 4096
#define NH 32
#define NG 8
#define HD 128
#define KV_DIM 1024
#define QKV_N (MODEL_DIM + 2 * KV_DIM)    // 6144
#define S_LEN 2048

// ---------------- scratch (__device__ globals; no allocs allowed) ----------
__device__ float4 g_xpk[(S_LEN / 16) * (MODEL_DIM / 8) * 32];       // packed x
__device__ float4 g_apk[(S_LEN / 16) * (MODEL_DIM / 8) * 32];       // packed attn out
__device__ float4 g_wqkvpk[(QKV_N / 16) * (MODEL_DIM / 8) * 32];    // packed Wqkv^T
__device__ float4 g_wopk[(MODEL_DIM / 16) * (MODEL_DIM / 8) * 32];  // packed Wo^T
__device__ float2 g_rope[S_LEN * 64];                               // {cos, sin}
// pre-split bf16 operands for attention (packed per head: [h][s][d])
__device__ __nv_bfloat16 g_qhi[NH * S_LEN * HD];
__device__ __nv_bfloat16 g_qlo[NH * S_LEN * HD];
__device__ __nv_bfloat16 g_khi[NG * S_LEN * HD];
__device__ __nv_bfloat16 g_klo[NG * S_LEN * HD];
__device__ __nv_bfloat16 g_vhi[NG * S_LEN * HD];
__device__ __nv_bfloat16 g_vlo[NG * S_LEN * HD];

// ---------------- helpers --------------------------------------------------
__device__ __forceinline__ uint32_t f2tf32(float x) {
    uint32_t t;
    asm("cvt.rna.tf32.f32 %0, %1;" : "=r"(t) : "f"(x));
    return t;
}
__device__ __forceinline__ float tf32r(float x) { return __uint_as_float(f2tf32(x)); }

__device__ __forceinline__ void mma_tf32(float c[4],
                                         uint32_t a0, uint32_t a1, uint32_t a2, uint32_t a3,
                                         uint32_t b0, uint32_t b1) {
    asm volatile(
        "mma.sync.aligned.m16n8k8.row.col.f32.tf32.tf32.f32 "
        "{%0,%1,%2,%3}, {%4,%5,%6,%7}, {%8,%9}, {%0,%1,%2,%3};\n"
        : "+f"(c[0]), "+f"(c[1]), "+f"(c[2]), "+f"(c[3])
        : "r"(a0), "r"(a1), "r"(a2), "r"(a3), "r"(b0), "r"(b1));
}

__device__ __forceinline__ void cp_async16(uint32_t smem_addr, const void* gptr) {
    asm volatile("cp.async.cg.shared.global [%0], [%1], 16;\n"
                 :: "r"(smem_addr), "l"(gptr));
}

__device__ __forceinline__ void split_bf16(float x, __nv_bfloat16& hi, __nv_bfloat16& lo) {
    hi = __float2bfloat16(x);
    lo = __float2bfloat16(x - __bfloat162float(hi));
}

__device__ __forceinline__ uint32_t pack_bf16x2(__nv_bfloat16 a, __nv_bfloat16 b) {
    __nv_bfloat162 t{a, b};
    return *(uint32_t*)&t;
}

// ---------------------------------------------------------------------------
// RoPE trig table (fp64, computed once per call).
// ---------------------------------------------------------------------------
__global__ __launch_bounds__(64) void rope_table_kernel()
{
    int s = blockIdx.x;
    int d = threadIdx.x;
    double inv = pow(50000.0, -2.0 * (double)d / 128.0);
    double ang = (double)s * inv;
    g_rope[s * 64 + d] = float2{(float)cos(ang), (float)sin(ang)};
}

// ---------------------------------------------------------------------------
// Coalesced packing via 64x64 smem transpose tiles (bit-identical values).
// ---------------------------------------------------------------------------
__global__ __launch_bounds__(256) void pack_a_t_kernel(
    const float* __restrict__ A, float4* __restrict__ pk, int M, int K)
{
    __shared__ float ts[64][68];
    const int tid = threadIdx.x;
    const int m0 = blockIdx.y * 64;
    const int k0 = blockIdx.x * 64;
    const int Kt = K >> 3;

#pragma unroll
    for (int i = 0; i < 4; i++) {
        int idx = tid + i * 256;
        int r  = idx >> 4;
        int c4 = (idx & 15) * 4;
        *(float4*)&ts[r][c4] = *(const float4*)&A[(size_t)(m0 + r) * K + k0 + c4];
    }
    __syncthreads();

#pragma unroll
    for (int i = 0; i < 4; i++) {
        int idx  = tid + i * 256;
        int lane = idx & 31;
        int ktl  = (idx >> 5) & 7;
        int mtl  = idx >> 8;
        int rl = mtl * 16 + (lane >> 2);
        int cl = ktl * 8 + (lane & 3);
        float4 v;
        v.x = tf32r(ts[rl][cl]);
        v.y = tf32r(ts[rl + 8][cl]);
        v.z = tf32r(ts[rl][cl + 4]);
        v.w = tf32r(ts[rl + 8][cl + 4]);
        size_t mt_g = (size_t)(m0 >> 4) + mtl;
        size_t kt_g = (size_t)(k0 >> 3) + ktl;
        pk[(mt_g * Kt + kt_g) * 32 + lane] = v;
    }
}

__global__ __launch_bounds__(256) void pack_b_t_kernel(
    const float* __restrict__ W, float4* __restrict__ pk, int K, int N)
{
    __shared__ float ts[64][72];
    const int tid = threadIdx.x;
    const int n0 = blockIdx.x * 64;
    const int k0 = blockIdx.y * 64;
    const int Kt = K >> 3;

#pragma unroll
    for (int i = 0; i < 4; i++) {
        int idx = tid + i * 256;
        int r  = idx >> 4;
        int c4 = (idx & 15) * 4;
        *(float4*)&ts[r][c4] = *(const float4*)&W[(size_t)(k0 + r) * N + n0 + c4];
    }
    __syncthreads();

#pragma unroll
    for (int i = 0; i < 4; i++) {
        int idx  = tid + i * 256;
        int lane = idx & 31;
        int ktl  = (idx >> 5) & 7;
        int npl  = idx >> 8;
        int kl = ktl * 8 + (lane & 3);
        int nl = npl * 16 + (lane >> 2);
        float4 v;
        v.x = tf32r(ts[kl][nl]);
        v.y = tf32r(ts[kl + 4][nl]);
        v.z = tf32r(ts[kl][nl + 8]);
        v.w = tf32r(ts[kl + 4][nl + 8]);
        size_t np_g = (size_t)(n0 >> 4) + npl;
        size_t kt_g = (size_t)(k0 >> 3) + ktl;
        pk[(np_g * Kt + kt_g) * 32 + lane] = v;
    }
}

// ---------------------------------------------------------------------------
// Fragment-packed TF32 GEMM (R13): CTA 128x128, 128 threads, 4 warps of 64x64,
// 2-stage cp.async, 3 CTAs/SM.
// ---------------------------------------------------------------------------
#define GEMM_SMEM (2 * 2048 * 16)   // 65536 B

template<int FUSED>
__global__ __launch_bounds__(128, 3) void gemm_pk_kernel(
    const float4* __restrict__ Apk, const float4* __restrict__ Bpk,
    const float* __restrict__ bias, float* __restrict__ C,
    int M, int N, int K)
{
    extern __shared__ float4 sm4[];
    const int tid  = threadIdx.x;
    const int warp = tid >> 5;
    const int lane = tid & 31;
    const int wm = warp & 1;
    const int wn = warp >> 1;
    const int bm = blockIdx.y * 128;
    const int bn = blockIdx.x * 128;
    const int Kt = K >> 3;
    const uint32_t sbase = (uint32_t)__cvta_generic_to_shared(sm4);

    float acc[4][8][4];
#pragma unroll
    for (int mt = 0; mt < 4; mt++)
#pragma unroll
        for (int nt = 0; nt < 8; nt++)
#pragma unroll
            for (int e = 0; e < 4; e++) acc[mt][nt][e] = 0.f;

    auto load_stage = [&](int buf, int kt0) {
#pragma unroll
        for (int t = 0; t < 8; t++) {
            int c = tid + t * 128;
            int unit = c >> 7, win = c & 127;
            const float4* g = Apk + ((size_t)((bm >> 4) + unit) * Kt + kt0) * 32 + win;
            cp_async16(sbase + (uint32_t)(buf * 2048 + c) * 16, g);
        }
#pragma unroll
        for (int t = 0; t < 8; t++) {
            int c = tid + t * 128;
            int unit = c >> 7, win = c & 127;
            const float4* g = Bpk + ((size_t)((bn >> 4) + unit) * Kt + kt0) * 32 + win;
            cp_async16(sbase + (uint32_t)(buf * 2048 + 1024 + c) * 16, g);
        }
        asm volatile("cp.async.commit_group;\n");
    };

    load_stage(0, 0);

    const int NSt = K >> 5;
    for (int ks = 0; ks < NSt; ks++) {
        if (ks + 1 < NSt) {
            load_stage((ks + 1) & 1, (ks + 1) * 4);
            asm volatile("cp.async.wait_group 1;\n");
        } else {
            asm volatile("cp.async.wait_group 0;\n");
        }
        __syncthreads();

        const float4* As_ = sm4 + (ks & 1) * 2048;
        const float4* Bs_ = As_ + 1024;

#pragma unroll
        for (int kk = 0; kk < 4; kk++) {
            float4 a[4];
#pragma unroll
            for (int mt = 0; mt < 4; mt++)
                a[mt] = As_[((wm * 4 + mt) * 4 + kk) * 32 + lane];
#pragma unroll
            for (int np = 0; np < 4; np++) {
                float4 b = Bs_[((wn * 4 + np) * 4 + kk) * 32 + lane];
                uint32_t b0 = __float_as_uint(b.x);
                uint32_t b1 = __float_as_uint(b.y);
                uint32_t b2 = __float_as_uint(b.z);
                uint32_t b3 = __float_as_uint(b.w);
#pragma unroll
                for (int mt = 0; mt < 4; mt++) {
                    mma_tf32(acc[mt][2 * np],
                             __float_as_uint(a[mt].x), __float_as_uint(a[mt].y),
                             __float_as_uint(a[mt].z), __float_as_uint(a[mt].w),
                             b0, b1);
                    mma_tf32(acc[mt][2 * np + 1],
                             __float_as_uint(a[mt].x), __float_as_uint(a[mt].y),
                             __float_as_uint(a[mt].z), __float_as_uint(a[mt].w),
                             b2, b3);
                }
            }
        }
        __syncthreads();
    }

    if (FUSED == 0) {
#pragma unroll
        for (int mt = 0; mt < 4; mt++) {
            int r0 = bm + wm * 64 + mt * 16 + (lane >> 2);
#pragma unroll
            for (int np = 0; np < 4; np++) {
#pragma unroll
                for (int q = 0; q < 2; q++) {
                    int nt = 2 * np + q;
                    int c = bn + wn * 64 + np * 16 + q * 8 + (lane & 3) * 2;
                    float2 bv = *(const float2*)&bias[c];
                    float2 o0, o1;
                    o0.x = acc[mt][nt][0] + bv.x;
                    o0.y = acc[mt][nt][1] + bv.y;
                    o1.x = acc[mt][nt][2] + bv.x;
                    o1.y = acc[mt][nt][3] + bv.y;
                    *(float2*)&C[(size_t)r0 * N + c]       = o0;
                    *(float2*)&C[(size_t)(r0 + 8) * N + c] = o1;
                }
            }
        }
    } else {
        __syncthreads();
        float* So = (float*)sm4;   // [128][128] fp32 = 64KB
#pragma unroll
        for (int mt = 0; mt < 4; mt++) {
            int rl = wm * 64 + mt * 16 + (lane >> 2);
#pragma unroll
            for (int np = 0; np < 4; np++) {
#pragma unroll
                for (int q = 0; q < 2; q++) {
                    int nt = 2 * np + q;
                    int cl = wn * 64 + np * 16 + q * 8 + (lane & 3) * 2;
                    float2 bv = *(const float2*)&bias[bn + cl];
                    So[rl * 128 + cl]           = acc[mt][nt][0] + bv.x;
                    So[rl * 128 + cl + 1]       = acc[mt][nt][1] + bv.y;
                    So[(rl + 8) * 128 + cl]     = acc[mt][nt][2] + bv.x;
                    So[(rl + 8) * 128 + cl + 1] = acc[mt][nt][3] + bv.y;
                }
            }
        }
        __syncthreads();

        __nv_bfloat16 *dhi, *dlo;
        int mode;
        size_t base;
        if (bn < MODEL_DIM)               { dhi = g_qhi; dlo = g_qlo; base = (size_t)(bn >> 7) * S_LEN * HD; mode = 2; }
        else if (bn < MODEL_DIM + KV_DIM) { dhi = g_khi; dlo = g_klo; base = (size_t)((bn - MODEL_DIM) >> 7) * S_LEN * HD; mode = 1; }
        else                              { dhi = g_vhi; dlo = g_vlo; base = (size_t)((bn - MODEL_DIM - KV_DIM) >> 7) * S_LEN * HD; mode = 0; }
        const float scale = 0.08838834764831843f;

#pragma unroll
        for (int it = 0; it < 32; it++) {
            int idx = tid + it * 128;
            int r = idx >> 5;
            int dp = (idx & 31) * 2;
            int s = bm + r;
            float x1a = So[r * 128 + dp];
            float x1b = So[r * 128 + dp + 1];
            float x2a = So[r * 128 + dp + 64];
            float x2b = So[r * 128 + dp + 65];
            float r1a, r2a, r1b, r2b;
            if (mode == 0) {
                r1a = x1a; r2a = x2a; r1b = x1b; r2b = x2b;
            } else {
                float2 cs0 = g_rope[s * 64 + dp];
                float2 cs1 = g_rope[s * 64 + dp + 1];
                r1a = x1a * cs0.x - x2a * cs0.y;
                r2a = x2a * cs0.x + x1a * cs0.y;
                r1b = x1b * cs1.x - x2b * cs1.y;
                r2b = x2b * cs1.x + x1b * cs1.y;
                if (mode == 2) { r1a *= scale; r2a *= scale; r1b *= scale; r2b *= scale; }
            }
            __nv_bfloat16 h0, l0, h1, l1;
            size_t o = base + (size_t)s * HD + dp;
            split_bf16(r1a, h0, l0); split_bf16(r1b, h1, l1);
            *(__nv_bfloat162*)&dhi[o] = __nv_bfloat162{h0, h1};
            *(__nv_bfloat162*)&dlo[o] = __nv_bfloat162{l0, l1};
            split_bf16(r2a, h0, l0); split_bf16(r2b, h1, l1);
            *(__nv_bfloat162*)&dhi[o + 64] = __nv_bfloat162{h0, h1};
            *(__nv_bfloat162*)&dlo[o + 64] = __nv_bfloat162{l0, l1};
        }
    }
}

// ---------------------------------------------------------------------------
// bf16x3 mma.sync flash attention, occupancy-optimized:
// CTA = 128 threads (4 warps), q-tile 64 rows, KV blocks 32 rows,
// double-buffered cp.async; 2 CTAs/SM (two barrier domains overlap).
// Q and P fragments in registers; fused packed epilogue.
// ---------------------------------------------------------------------------
#define AQ_STRIDE 136
#define KVB_E (4 * 32 * AQ_STRIDE)          // 17408 elems per 32-row KV stage
#define ATTN_SMEM_BYTES (2 * KVB_E * 2)     // 69632 B

#define LDSM4(R0,R1,R2,R3,ADDR) \
    asm volatile("ldmatrix.sync.aligned.m8n8.x4.shared.b16 {%0,%1,%2,%3}, [%4];" \
                 : "=r"(R0),"=r"(R1),"=r"(R2),"=r"(R3) : "r"(ADDR))
#define LDSM4T(R0,R1,R2,R3,ADDR) \
    asm volatile("ldmatrix.sync.aligned.m8n8.x4.trans.shared.b16 {%0,%1,%2,%3}, [%4];" \
                 : "=r"(R0),"=r"(R1),"=r"(R2),"=r"(R3) : "r"(ADDR))

__device__ __forceinline__ void mma_bf16(float c[4],
                                         uint32_t a0, uint32_t a1, uint32_t a2, uint32_t a3,
                                         uint32_t b0, uint32_t b1) {
    asm volatile(
        "mma.sync.aligned.m16n8k16.row.col.f32.bf16.bf16.f32 "
        "{%0,%1,%2,%3}, {%4,%5,%6,%7}, {%8,%9}, {%0,%1,%2,%3};\n"
        : "+f"(c[0]), "+f"(c[1]), "+f"(c[2]), "+f"(c[3])
        : "r"(a0), "r"(a1), "r"(a2), "r"(a3), "r"(b0), "r"(b1));
}

__global__ __launch_bounds__(128, 2) void attn_mma_kernel(float4* __restrict__ apk)
{
    extern __shared__ __nv_bfloat16 sbm[];
    const uint32_t sb = (uint32_t)__cvta_generic_to_shared(sbm);

    const int tid  = threadIdx.x;
    const int warp = tid >> 5;
    const int lane = tid & 31;
    const int mb = (gridDim.x - 1) - blockIdx.x;   // heavy tiles first
    const int h  = blockIdx.y;
    const int kvh = h >> 2;
    const int m0 = mb * 64;

    const __nv_bfloat16* kh_base = g_khi + (size_t)kvh * S_LEN * HD;
    const __nv_bfloat16* kl_base = g_klo + (size_t)kvh * S_LEN * HD;
    const __nv_bfloat16* vh_base = g_vhi + (size_t)kvh * S_LEN * HD;
    const __nv_bfloat16* vl_base = g_vlo + (size_t)kvh * S_LEN * HD;

    auto kv_load = [&](int b, int k0) {
        const uint32_t arr = (uint32_t)(32 * AQ_STRIDE * 2);   // bytes per sub-array
#pragma unroll
        for (int t = 0; t < 4; t++) {
            int idx = tid + t * 128;
            int r  = idx >> 4;            // 0..31
            int c8 = (idx & 15) * 8;
            size_t go = (size_t)(k0 + r) * HD + c8;
            uint32_t so = sb + (uint32_t)(b * KVB_E * 2 + (r * AQ_STRIDE + c8) * 2);
            cp_async16(so,           kh_base + go);
            cp_async16(so + arr,     kl_base + go);
            cp_async16(so + 2 * arr, vh_base + go);
            cp_async16(so + 3 * arr, vl_base + go);
        }
        asm volatile("cp.async.commit_group;\n");
    };

    // ---- prefetch KV block 0 into buf0, overlapping the Q prologue ----
    kv_load(0, 0);

    // ---- stage Q (64 rows) in buf1 region, load fragments to registers ----
    {
        __nv_bfloat16* Qst_hi = sbm + KVB_E;
        __nv_bfloat16* Qst_lo = sbm + KVB_E + 64 * AQ_STRIDE;
        const __nv_bfloat16* qh = g_qhi + ((size_t)h * S_LEN + m0) * HD;
        const __nv_bfloat16* ql = g_qlo + ((size_t)h * S_LEN + m0) * HD;
#pragma unroll
        for (int t = 0; t < 8; t++) {
            int idx = tid + t * 128;
            int r  = idx >> 4;            // 0..63
            int c8 = (idx & 15) * 8;
            *(uint4*)&Qst_hi[r * AQ_STRIDE + c8] = *(const uint4*)&qh[r * HD + c8];
            *(uint4*)&Qst_lo[r * AQ_STRIDE + c8] = *(const uint4*)&ql[r * HD + c8];
        }
    }
    __syncthreads();

    uint32_t aqh[8][4], aql[8][4];
    const int a_row = warp * 16 + (lane & 15);
    const int a_col8 = (lane >> 4) * 8;
#pragma unroll
    for (int ks = 0; ks < 8; ks++) {
        uint32_t ad = sb + (uint32_t)(KVB_E * 2) +
                      (uint32_t)((a_row * AQ_STRIDE + ks * 16 + a_col8) * 2);
        LDSM4(aqh[ks][0], aqh[ks][1], aqh[ks][2], aqh[ks][3], ad);
        ad += (uint32_t)(64 * AQ_STRIDE * 2);
        LDSM4(aql[ks][0], aql[ks][1], aql[ks][2], aql[ks][3], ad);
    }
    __syncthreads();   // Q frags extracted; buf1 free for kv_load(1)

    float mrow[2] = {-1e30f, -1e30f};
    float lrow[2] = {0.f, 0.f};
    float oacc[16][4];
#pragma unroll
    for (int nt = 0; nt < 16; nt++)
#pragma unroll
        for (int e = 0; e < 4; e++) oacc[nt][e] = 0.f;

    const int row0g = m0 + warp * 16 + (lane >> 2);
    const int row1g = row0g + 8;

    const int nkb = 2 * mb + 2;   // kv blocks of 32 rows, covers rows <= m0+63
    for (int kb = 0; kb < nkb; kb++) {
        const int cur = kb & 1;
        asm volatile("cp.async.wait_group 0;\n");
        __syncthreads();
        if (kb + 1 < nkb) kv_load(1 - cur, (kb + 1) * 32);

        const __nv_bfloat16* KhiC = sbm + cur * KVB_E;
        const __nv_bfloat16* KloC = KhiC + 32 * AQ_STRIDE;
        const __nv_bfloat16* VhiC = KhiC + 2 * 32 * AQ_STRIDE;
        const __nv_bfloat16* VloC = KhiC + 3 * 32 * AQ_STRIDE;
        const int k0 = kb * 32;

        // ---- S = Q K^T (bf16x3, Q in regs); 32 kv cols -> 4 n8 tiles ----
        float sacc[4][4];
#pragma unroll
        for (int nt = 0; nt < 4; nt++)
#pragma unroll
            for (int e = 0; e < 4; e++) sacc[nt][e] = 0.f;

#pragma unroll
        for (int ks = 0; ks < 8; ks++) {
#pragma unroll
            for (int ng = 0; ng < 2; ng++) {
                uint32_t bh[4], bl[4];
                uint32_t bd = (uint32_t)__cvta_generic_to_shared(
                    &KhiC[(ng * 16 + (lane & 15)) * AQ_STRIDE + ks * 16 + a_col8]);
                LDSM4(bh[0], bh[1], bh[2], bh[3], bd);
                bd = (uint32_t)__cvta_generic_to_shared(
                    &KloC[(ng * 16 + (lane & 15)) * AQ_STRIDE + ks * 16 + a_col8]);
                LDSM4(bl[0], bl[1], bl[2], bl[3], bd);
                int nt = ng * 2;
                mma_bf16(sacc[nt],   aqh[ks][0],aqh[ks][1],aqh[ks][2],aqh[ks][3], bh[0],bh[2]);
                mma_bf16(sacc[nt],   aqh[ks][0],aqh[ks][1],aqh[ks][2],aqh[ks][3], bl[0],bl[2]);
                mma_bf16(sacc[nt],   aql[ks][0],aql[ks][1],aql[ks][2],aql[ks][3], bh[0],bh[2]);
                mma_bf16(sacc[nt+1], aqh[ks][0],aqh[ks][1],aqh[ks][2],aqh[ks][3], bh[1],bh[3]);
                mma_bf16(sacc[nt+1], aqh[ks][0],aqh[ks][1],aqh[ks][2],aqh[ks][3], bl[1],bl[3]);
                mma_bf16(sacc[nt+1], aql[ks][0],aql[ks][1],aql[ks][2],aql[ks][3], bh[1],bh[3]);
            }
        }

        // ---- causal mask ----
        if (k0 + 31 > m0) {
#pragma unroll
            for (int nt = 0; nt < 4; nt++) {
                int c = k0 + nt * 8 + 2 * (lane & 3);
                if (c     > row0g) sacc[nt][0] = -1e30f;
                if (c + 1 > row0g) sacc[nt][1] = -1e30f;
                if (c     > row1g) sacc[nt][2] = -1e30f;
                if (c + 1 > row1g) sacc[nt][3] = -1e30f;
            }
        }

        // ---- online softmax (warp-local); P packed into registers ----
        float mx0 = -1e30f, mx1 = -1e30f;
#pragma unroll
        for (int nt = 0; nt < 4; nt++) {
            mx0 = fmaxf(mx0, fmaxf(sacc[nt][0], sacc[nt][1]));
            mx1 = fmaxf(mx1, fmaxf(sacc[nt][2], sacc[nt][3]));
        }
        mx0 = fmaxf(mx0, __shfl_xor_sync(0xffffffffu, mx0, 1));
        mx0 = fmaxf(mx0, __shfl_xor_sync(0xffffffffu, mx0, 2));
        mx1 = fmaxf(mx1, __shfl_xor_sync(0xffffffffu, mx1, 1));
        mx1 = fmaxf(mx1, __shfl_xor_sync(0xffffffffu, mx1, 2));

        float mn0 = fmaxf(mrow[0], mx0);
        float mn1 = fmaxf(mrow[1], mx1);
        float al0 = __expf(mrow[0] - mn0);
        float al1 = __expf(mrow[1] - mn1);

        uint32_t pfh[4], pfh2[4], pfl[4], pfl2[4];
        float s0 = 0.f, s1 = 0.f;
#pragma unroll
        for (int nt = 0; nt < 4; nt++) {
            float p00 = __expf(sacc[nt][0] - mn0);
            float p01 = __expf(sacc[nt][1] - mn0);
            float p10 = __expf(sacc[nt][2] - mn1);
            float p11 = __expf(sacc[nt][3] - mn1);
            s0 += p00 + p01;
            s1 += p10 + p11;
            __nv_bfloat16 h0,l0,h1,l1;
            split_bf16(p00,h0,l0); split_bf16(p01,h1,l1);
            pfh[nt] = pack_bf16x2(h0,h1); pfl[nt] = pack_bf16x2(l0,l1);
            split_bf16(p10,h0,l0); split_bf16(p11,h1,l1);
            pfh2[nt] = pack_bf16x2(h0,h1); pfl2[nt] = pack_bf16x2(l0,l1);
        }
        s0 += __shfl_xor_sync(0xffffffffu, s0, 1);
        s0 += __shfl_xor_sync(0xffffffffu, s0, 2);
        s1 += __shfl_xor_sync(0xffffffffu, s1, 1);
        s1 += __shfl_xor_sync(0xffffffffu, s1, 2);

        lrow[0] = lrow[0] * al0 + s0;
        lrow[1] = lrow[1] * al1 + s1;
        mrow[0] = mn0;
        mrow[1] = mn1;
#pragma unroll
        for (int nt = 0; nt < 16; nt++) {
            oacc[nt][0] *= al0; oacc[nt][1] *= al0;
            oacc[nt][2] *= al1; oacc[nt][3] *= al1;
        }

        // ---- O += P V (bf16x3, P from registers); 32 kv rows = 2 k16 ----
        const int v_row = (lane & 7) + 8 * ((lane >> 3) & 1);
        const int v_col8 = 8 * (lane >> 4);
#pragma unroll
        for (int ks = 0; ks < 2; ks++) {
            int kk = ks * 16;
            uint32_t ah0 = pfh[2*ks],  ah1 = pfh2[2*ks],  ah2 = pfh[2*ks+1],  ah3 = pfh2[2*ks+1];
            uint32_t al0_ = pfl[2*ks], al1_ = pfl2[2*ks], al2_ = pfl[2*ks+1], al3_ = pfl2[2*ks+1];
#pragma unroll
            for (int dg = 0; dg < 8; dg++) {
                int db = dg * 16;
                uint32_t vh[4], vl[4];
                uint32_t vd = (uint32_t)__cvta_generic_to_shared(
                    &VhiC[(kk + v_row) * AQ_STRIDE + db + v_col8]);
                LDSM4T(vh[0], vh[1], vh[2], vh[3], vd);
                vd = (uint32_t)__cvta_generic_to_shared(
                    &VloC[(kk + v_row) * AQ_STRIDE + db + v_col8]);
                LDSM4T(vl[0], vl[1], vl[2], vl[3], vd);
                int nt = dg * 2;
                mma_bf16(oacc[nt],   ah0,ah1,ah2,ah3, vh[0],vh[1]);
                mma_bf16(oacc[nt],   ah0,ah1,ah2,ah3, vl[0],vl[1]);
                mma_bf16(oacc[nt],   al0_,al1_,al2_,al3_, vh[0],vh[1]);
                mma_bf16(oacc[nt+1], ah0,ah1,ah2,ah3, vh[2],vh[3]);
                mma_bf16(oacc[nt+1], ah0,ah1,ah2,ah3, vl[2],vl[3]);
                mma_bf16(oacc[nt+1], al0_,al1_,al2_,al3_, vh[2],vh[3]);
            }
        }
    }

    // ---- epilogue: normalize -> smem staging -> fragment-packed apk ----
    __syncthreads();
    float* So = (float*)sbm;   // [64][132] fp32 = 33.8KB
    {
        float inv0 = 1.f / lrow[0];
        float inv1 = 1.f / lrow[1];
        int r0l = warp * 16 + (lane >> 2);
#pragma unroll
        for (int nt = 0; nt < 16; nt++) {
            int col = nt * 8 + 2 * (lane & 3);
            So[r0l * 132 + col]           = oacc[nt][0] * inv0;
            So[r0l * 132 + col + 1]       = oacc[nt][1] * inv0;
            So[(r0l + 8) * 132 + col]     = oacc[nt][2] * inv1;
            So[(r0l + 8) * 132 + col + 1] = oacc[nt][3] * inv1;
        }
    }
    __syncthreads();

    {
        const int Ktot = MODEL_DIM / 8;   // 512
#pragma unroll
        for (int i = 0; i < 16; i++) {
            int idx = tid + i * 128;        // 0..2047
            int lane2 = idx & 31;
            int kt_l  = (idx >> 5) & 15;
            int mt_l  = idx >> 9;           // 0..3 (16-row units of the 64-row tile)
            int r = mt_l * 16 + (lane2 >> 2);
            int c = kt_l * 8 + (lane2 & 3);
            float4 v;
            v.x = tf32r(So[r * 132 + c]);
            v.y = tf32r(So[(r + 8) * 132 + c]);
            v.z = tf32r(So[r * 132 + c + 4]);
            v.w = tf32r(So[(r + 8) * 132 + c + 4]);
            size_t mt_g = (size_t)(m0 >> 4) + mt_l;
            size_t kt_g = (size_t)h * 16 + kt_l;
            apk[(mt_g * Ktot + kt_g) * 32 + lane2] = v;
        }
    }
}

// ---------------------------------------------------------------------------
extern "C" void kernel_launch(void* const* d_in, const int* in_sizes, int n_in,
                              void* d_out, int out_size)
{
    const float* x    = (const float*)d_in[0];
    const float* Wqkv = (const float*)d_in[1];
    const float* bqkv = (const float*)d_in[2];
    const float* Wo   = (const float*)d_in[3];
    const float* bo   = (const float*)d_in[4];
    float* out = (float*)d_out;

    float4 *xpk, *apk, *wqpk, *wopk;
    cudaGetSymbolAddress((void**)&xpk, g_xpk);
    cudaGetSymbolAddress((void**)&apk, g_apk);
    cudaGetSymbolAddress((void**)&wqpk, g_wqkvpk);
    cudaGetSymbolAddress((void**)&wopk, g_wopk);

    cudaFuncSetAttribute(gemm_pk_kernel<0>,
                         cudaFuncAttributeMaxDynamicSharedMemorySize, GEMM_SMEM);
    cudaFuncSetAttribute(gemm_pk_kernel<1>,
                         cudaFuncAttributeMaxDynamicSharedMemorySize, GEMM_SMEM);
    cudaFuncSetAttribute(attn_mma_kernel,
                         cudaFuncAttributeMaxDynamicSharedMemorySize, ATTN_SMEM_BYTES);

    static cudaStream_t s_side = nullptr;
    static cudaEvent_t e_fork = nullptr, e_rope = nullptr, e_packs = nullptr, e_wo = nullptr;
    if (!s_side) {
        cudaStreamCreateWithFlags(&s_side, cudaStreamNonBlocking);
        cudaEventCreateWithFlags(&e_fork,  cudaEventDisableTiming);
        cudaEventCreateWithFlags(&e_rope,  cudaEventDisableTiming);
        cudaEventCreateWithFlags(&e_packs, cudaEventDisableTiming);
        cudaEventCreateWithFlags(&e_wo,    cudaEventDisableTiming);
    }

    // ---- fork: side stream runs the tiny rope table first ----
    cudaEventRecord(e_fork, 0);
    cudaStreamWaitEvent(s_side, e_fork, 0);
    rope_table_kernel<<<S_LEN, 64, 0, s_side>>>();
    cudaEventRecord(e_rope, s_side);

    // ---- main stream: critical packs get full DRAM bandwidth ----
    pack_a_t_kernel<<<dim3(MODEL_DIM / 64, S_LEN / 64), 256>>>(x, xpk, S_LEN, MODEL_DIM);
    pack_b_t_kernel<<<dim3(QKV_N / 64, MODEL_DIM / 64), 256>>>(Wqkv, wqpk, MODEL_DIM, QKV_N);
    cudaEventRecord(e_packs, 0);

    // side stream: Wo pack after critical packs -> overlaps compute-bound QKV GEMM
    cudaStreamWaitEvent(s_side, e_packs, 0);
    pack_b_t_kernel<<<dim3(MODEL_DIM / 64, MODEL_DIM / 64), 256, 0, s_side>>>(
        Wo, wopk, MODEL_DIM, MODEL_DIM);
    cudaEventRecord(e_wo, s_side);

    // join rope table (QKV epilogue reads it)
    cudaStreamWaitEvent(0, e_rope, 0);

    // 1) QKV projection with fused RoPE + bf16 split epilogue
    gemm_pk_kernel<1><<<dim3(QKV_N / 128, S_LEN / 128), 128, GEMM_SMEM>>>(
        xpk, wqpk, bqkv, nullptr, S_LEN, QKV_N, MODEL_DIM);

    // 2) attention (bf16x3 mma.sync, 64-row q-tiles, 2 CTAs/SM) -> packed tf32
    attn_mma_kernel<<<dim3(S_LEN / 64, NH), 128, ATTN_SMEM_BYTES>>>(apk);

    // join Wo pack before O-proj
    cudaStreamWaitEvent(0, e_wo, 0);

    // 3) output projection
    gemm_pk_kernel<0><<<dim3(MODEL_DIM / 128, S_LEN / 128), 128, GEMM_SMEM>>>(
        apk, wopk, bo, out, S_LEN, MODEL_DIM, MODEL_DIM);
}